// round 1
// baseline (speedup 1.0000x reference)
#include <cuda_runtime.h>
#include <math.h>

#define NN 512
#define DF 256

// ---------------- scratch (device globals; no runtime alloc) ----------------
__device__ float g_Wh1[NN*DF];
__device__ float g_e0[NN], g_e1[NN];
__device__ float g_P[NN*NN];
__device__ float g_H1[NN*DF];
__device__ float g_Ar[NN*DF];
__device__ float g_Br[NN*DF];
__device__ float g_u[DF];
__device__ float g_red[512];
__device__ float g_MS[2];
__device__ float g_s2[NN*NN];
__device__ float g_gv[DF];
__device__ float g_H2v[64];
__device__ float g_X2[NN*512];
__device__ float g_hid[NN*DF];
__device__ float g_tf[NN*64];
__device__ float g_H3[NN*64];
__device__ int   g_i0[NN], g_i1[NN];
__device__ float g_X3[NN*768];
__device__ float g_cf[NN*64];
__device__ float g_H4v[64];
__device__ float g_X4[NN*385];
__device__ float g_Z[NN*DF];
__device__ float g_pre[NN*DF];
__device__ float g_slab[4*NN*DF];   // split-K slabs / pair partials (reused)

// ---------------- GEMM C = A(MxK) * B(NxK)^T, split-K into slabs ----------------
__global__ __launch_bounds__(256) void gemm_nt_k(
    const float* __restrict__ A, int lda,
    const float* __restrict__ B, int ldb,
    int M, int N, int K, int ksplit)
{
    __shared__ __align__(16) float sA[16][68];
    __shared__ __align__(16) float sB[16][68];
    int tid = threadIdx.x;
    int tx = tid & 15, ty = tid >> 4;
    int m0 = blockIdx.y * 64, n0 = blockIdx.x * 64;
    int k0 = blockIdx.z * ksplit;
    int k1 = min(K, k0 + ksplit);
    float acc[4][4];
#pragma unroll
    for (int i = 0; i < 4; i++)
#pragma unroll
        for (int j = 0; j < 4; j++) acc[i][j] = 0.f;

    for (int kc = k0; kc < k1; kc += 16) {
#pragma unroll
        for (int s = 0; s < 4; s++) {
            int idx = tid + s * 256;
            int r = idx >> 4, k = idx & 15;
            int gk = kc + k;
            float av = (gk < k1) ? A[(m0 + r) * lda + gk] : 0.f;
            float bv = (gk < k1) ? B[(n0 + r) * ldb + gk] : 0.f;
            sA[k][r] = av;
            sB[k][r] = bv;
        }
        __syncthreads();
#pragma unroll
        for (int kk = 0; kk < 16; kk++) {
            float av[4], bv[4];
            *(float4*)av = *(const float4*)&sA[kk][ty << 2];
            *(float4*)bv = *(const float4*)&sB[kk][tx << 2];
#pragma unroll
            for (int i = 0; i < 4; i++)
#pragma unroll
                for (int j = 0; j < 4; j++)
                    acc[i][j] = fmaf(av[i], bv[j], acc[i][j]);
        }
        __syncthreads();
    }
    float* C = g_slab + blockIdx.z * (M * N);
#pragma unroll
    for (int i = 0; i < 4; i++)
#pragma unroll
        for (int j = 0; j < 4; j++)
            C[(m0 + ty * 4 + i) * N + (n0 + tx * 4 + j)] = acc[i][j];
}

// ---------------- GEMM C = A(MxK) * B(KxN), split-K into slabs ----------------
__global__ __launch_bounds__(256) void gemm_nn_k(
    const float* __restrict__ A, int lda,
    const float* __restrict__ B, int ldb,
    int M, int N, int K, int ksplit)
{
    __shared__ __align__(16) float sA[16][68];
    __shared__ __align__(16) float sB[16][68];
    int tid = threadIdx.x;
    int tx = tid & 15, ty = tid >> 4;
    int m0 = blockIdx.y * 64, n0 = blockIdx.x * 64;
    int k0 = blockIdx.z * ksplit;
    int k1 = min(K, k0 + ksplit);
    float acc[4][4];
#pragma unroll
    for (int i = 0; i < 4; i++)
#pragma unroll
        for (int j = 0; j < 4; j++) acc[i][j] = 0.f;

    for (int kc = k0; kc < k1; kc += 16) {
#pragma unroll
        for (int s = 0; s < 4; s++) {
            int idx = tid + s * 256;
            int r = idx >> 4, k = idx & 15;
            int gk = kc + k;
            sA[k][r] = (gk < k1) ? A[(m0 + r) * lda + gk] : 0.f;
            int kb = idx >> 6, nb = idx & 63;
            int gkb = kc + kb;
            sB[kb][nb] = (gkb < k1) ? B[gkb * ldb + n0 + nb] : 0.f;
        }
        __syncthreads();
#pragma unroll
        for (int kk = 0; kk < 16; kk++) {
            float av[4], bv[4];
            *(float4*)av = *(const float4*)&sA[kk][ty << 2];
            *(float4*)bv = *(const float4*)&sB[kk][tx << 2];
#pragma unroll
            for (int i = 0; i < 4; i++)
#pragma unroll
                for (int j = 0; j < 4; j++)
                    acc[i][j] = fmaf(av[i], bv[j], acc[i][j]);
        }
        __syncthreads();
    }
    float* C = g_slab + blockIdx.z * (M * N);
#pragma unroll
    for (int i = 0; i < 4; i++)
#pragma unroll
        for (int j = 0; j < 4; j++)
            C[(m0 + ty * 4 + i) * N + (n0 + tx * 4 + j)] = acc[i][j];
}

// sum 4 slabs + bias + act -> dst
__global__ __launch_bounds__(256) void finish_k(float* __restrict__ dst, int MN, int nmask,
                                                const float* __restrict__ bias, int act)
{
    int i = blockIdx.x * 256 + threadIdx.x;
    if (i >= MN) return;
    float v = g_slab[i] + g_slab[MN + i] + g_slab[2 * MN + i] + g_slab[3 * MN + i];
    if (bias) v += bias[i & nmask];
    if (act) v = fmaxf(v, 0.f);
    dst[i] = v;
}

// ---------------- GAT branch ----------------
__global__ __launch_bounds__(128) void e01_k(const float* __restrict__ sa0, const float* __restrict__ sa1)
{
    int w = threadIdx.x >> 5, lane = threadIdx.x & 31;
    int row = blockIdx.x * 4 + w;
    float a0 = 0.f, a1 = 0.f;
#pragma unroll
    for (int l = 0; l < 8; l++) {
        int k = lane + l * 32;
        float a = g_Wh1[row * 256 + k];
        a0 += a * sa0[k];
        a1 += a * sa1[k];
    }
#pragma unroll
    for (int o = 16; o > 0; o >>= 1) {
        a0 += __shfl_down_sync(0xffffffffu, a0, o);
        a1 += __shfl_down_sync(0xffffffffu, a1, o);
    }
    if (lane == 0) { g_e0[row] = a0; g_e1[row] = a1; }
}

__global__ __launch_bounds__(256) void gatP_k(const int* __restrict__ adj)
{
    int i = blockIdx.x;
    int tid = threadIdx.x;
    __shared__ float red[256];
    float e0i = g_e0[i];
    float sl[2];
    float m = -3.402823466e38f;
#pragma unroll
    for (int s = 0; s < 2; s++) {
        int j = tid + s * 256;
        float v = (adj[i * NN + j] != 0) ? (e0i + g_e1[j]) : -INFINITY;
        sl[s] = v;
        m = fmaxf(m, v);
    }
    red[tid] = m; __syncthreads();
    for (int o = 128; o > 0; o >>= 1) { if (tid < o) red[tid] = fmaxf(red[tid], red[tid + o]); __syncthreads(); }
    m = red[0]; __syncthreads();
    float e[2]; float sum = 0.f;
#pragma unroll
    for (int s = 0; s < 2; s++) { e[s] = expf(sl[s] - m); sum += e[s]; }
    red[tid] = sum; __syncthreads();
    for (int o = 128; o > 0; o >>= 1) { if (tid < o) red[tid] += red[tid + o]; __syncthreads(); }
    float inv = 1.f / red[0];
#pragma unroll
    for (int s = 0; s < 2; s++) g_P[i * NN + tid + s * 256] = e[s] * inv;
}

// ---------------- pair branch ----------------
__global__ __launch_bounds__(256) void u_k(const float* __restrict__ ce_w2,
                                           const float* __restrict__ ca0, const float* __restrict__ ca1)
{
    __shared__ float sc[64];
    int tid = threadIdx.x;
    if (tid < 64) sc[tid] = ca0[tid] + ca1[tid];
    __syncthreads();
    float acc = 0.f;
#pragma unroll 8
    for (int d = 0; d < 64; d++) acc += ce_w2[d * 256 + tid] * sc[d];
    g_u[tid] = acc;
}

// s2[i,j] = sum_k relu(Ar[i,k]+Br[j,k])*u[k]; diag -> -inf
// tile: 64 i x 32 j, micro 4x2, grid (16 jx, 8 iy)
__global__ __launch_bounds__(256) void pair_score_k()
{
    __shared__ __align__(16) float sA[16][68];
    __shared__ __align__(16) float sB[16][36];
    __shared__ float su[16];
    int tid = threadIdx.x;
    int tx = tid & 15, ty = tid >> 4;
    int ib = blockIdx.y * 64, jb = blockIdx.x * 32;
    float acc[4][2];
#pragma unroll
    for (int i = 0; i < 4; i++) { acc[i][0] = 0.f; acc[i][1] = 0.f; }
    for (int kc = 0; kc < 256; kc += 16) {
#pragma unroll
        for (int s = 0; s < 4; s++) {
            int idx = tid + s * 256;
            int r = idx >> 4, k = idx & 15;
            sA[k][r] = g_Ar[(ib + r) * 256 + kc + k];
        }
#pragma unroll
        for (int s = 0; s < 2; s++) {
            int idx = tid + s * 256;
            int r = idx >> 4, k = idx & 15;
            sB[k][r] = g_Br[(jb + r) * 256 + kc + k];
        }
        if (tid < 16) su[tid] = g_u[kc + tid];
        __syncthreads();
#pragma unroll
        for (int kk = 0; kk < 16; kk++) {
            float av[4], bv[2];
            *(float4*)av = *(const float4*)&sA[kk][ty << 2];
            *(float2*)bv = *(const float2*)&sB[kk][tx << 1];
            float uu = su[kk];
#pragma unroll
            for (int i = 0; i < 4; i++)
#pragma unroll
                for (int j = 0; j < 2; j++)
                    acc[i][j] += fmaxf(av[i] + bv[j], 0.f) * uu;
        }
        __syncthreads();
    }
#pragma unroll
    for (int i = 0; i < 4; i++)
#pragma unroll
        for (int j = 0; j < 2; j++) {
            int gi = ib + ty * 4 + i, gj = jb + tx * 2 + j;
            g_s2[gi * NN + gj] = (gi == gj) ? -INFINITY : acc[i][j];
        }
}

__global__ __launch_bounds__(256) void smax_part_k()
{
    int tid = threadIdx.x;
    int base = blockIdx.x * 1024;
    float m = -3.402823466e38f, sum = 0.f;
#pragma unroll
    for (int s = 0; s < 4; s++) {
        float x = g_s2[base + tid + s * 256];
        float nm = fmaxf(m, x);
        sum = sum * expf(m - nm) + expf(x - nm);
        m = nm;
    }
    __shared__ float sm[256], ss[256];
    sm[tid] = m; ss[tid] = sum; __syncthreads();
    for (int o = 128; o > 0; o >>= 1) {
        if (tid < o) {
            float m2 = sm[tid + o], s2v = ss[tid + o];
            float M = fmaxf(sm[tid], m2);
            ss[tid] = ss[tid] * expf(sm[tid] - M) + s2v * expf(m2 - M);
            sm[tid] = M;
        }
        __syncthreads();
    }
    if (tid == 0) { g_red[2 * blockIdx.x] = sm[0]; g_red[2 * blockIdx.x + 1] = ss[0]; }
}

__global__ __launch_bounds__(256) void smax_final_k()
{
    int tid = threadIdx.x;
    __shared__ float sm[256], ss[256];
    sm[tid] = g_red[2 * tid]; ss[tid] = g_red[2 * tid + 1];
    __syncthreads();
    for (int o = 128; o > 0; o >>= 1) {
        if (tid < o) {
            float m2 = sm[tid + o], s2v = ss[tid + o];
            float M = fmaxf(sm[tid], m2);
            ss[tid] = ss[tid] * expf(sm[tid] - M) + s2v * expf(m2 - M);
            sm[tid] = M;
        }
        __syncthreads();
    }
    if (tid == 0) { g_MS[0] = sm[0]; g_MS[1] = ss[0]; }
}

// partial g[k] per block: 8 rows i x 256 j-half, 256 threads over k. grid (64, 2)
__global__ __launch_bounds__(256) void pair_acc_k()
{
    int tid = threadIdx.x;
    int i0 = blockIdx.x * 8;
    int jb = blockIdx.y * 256;
    float M = g_MS[0], invS = 1.f / g_MS[1];
    float a[8];
#pragma unroll
    for (int ii = 0; ii < 8; ii++) a[ii] = g_Ar[(i0 + ii) * 256 + tid];
    float acc = 0.f;
    __shared__ float sw[8][32];
    int li = tid >> 5, lj = tid & 31;
    for (int jc = jb; jc < jb + 256; jc += 32) {
        sw[li][lj] = expf(g_s2[(i0 + li) * NN + jc + lj] - M) * invS;
        __syncthreads();
#pragma unroll 4
        for (int jj = 0; jj < 32; jj++) {
            float b = g_Br[(jc + jj) * 256 + tid];
#pragma unroll
            for (int ii = 0; ii < 8; ii++)
                acc += sw[ii][jj] * fmaxf(a[ii] + b, 0.f);
        }
        __syncthreads();
    }
    g_slab[(blockIdx.y * 64 + blockIdx.x) * 256 + tid] = acc;
}

__global__ __launch_bounds__(256) void gred_k()
{
    int tid = threadIdx.x;
    float acc = 0.f;
#pragma unroll 8
    for (int b = 0; b < 128; b++) acc += g_slab[b * 256 + tid];
    g_gv[tid] = acc;
}

__global__ __launch_bounds__(32) void h2_k(const float* __restrict__ ce_w2, const float* __restrict__ ce_b2)
{
    int d = blockIdx.x, lane = threadIdx.x;
    float acc = 0.f;
#pragma unroll
    for (int l = 0; l < 8; l++) {
        int k = lane + l * 32;
        acc += ce_w2[d * 256 + k] * g_gv[k];
    }
#pragma unroll
    for (int o = 16; o > 0; o >>= 1) acc += __shfl_down_sync(0xffffffffu, acc, o);
    if (lane == 0) g_H2v[d] = acc + ce_b2[d];
}

// ---------------- temporal branch ----------------
__global__ __launch_bounds__(256) void concat2_k(const float* __restrict__ V, const float* __restrict__ prev)
{
    int i = blockIdx.x, t = threadIdx.x;
    g_X2[i * 512 + t] = V[i * 256 + t];
    g_X2[i * 512 + 256 + t] = prev[i * 256 + t];
}

__global__ __launch_bounds__(64) void h3_k()
{
    int t = threadIdx.x;
    float acc = 0.f;
    for (int i = 0; i < NN; i++) {
        acc += g_tf[i * 64 + t];
        g_H3[i * 64 + t] = acc / (float)(i + 1);
    }
}

// ---------------- pair-encoder branch ----------------
__global__ __launch_bounds__(256) void neigh_k(const int* __restrict__ adj)
{
    int i = blockIdx.x * 256 + threadIdx.x;
    int a = NN, b = NN;
    for (int j = 0; j < NN; j++) {
        if (adj[i * NN + j] == 1) {
            if (a == NN) a = j;
            else { b = j; break; }
        }
    }
    g_i0[i] = a; g_i1[i] = b;
}

__global__ __launch_bounds__(256) void concat3_k(const float* __restrict__ V)
{
    int i = blockIdx.x, t = threadIdx.x;
    int i0 = g_i0[i], i1 = g_i1[i];
    int valid = (i1 < NN);
    int r0 = min(i0, NN - 1), r1 = min(i1, NN - 1);
    g_X3[i * 768 + t] = V[i * 256 + t];
    g_X3[i * 768 + 256 + t] = valid ? V[r0 * 256 + t] : 0.f;
    g_X3[i * 768 + 512 + t] = valid ? V[r1 * 256 + t] : 0.f;
}

__global__ __launch_bounds__(64) void h4_k()
{
    int t = threadIdx.x;
    float acc = 0.f;
    for (int i = 0; i < NN; i++) acc += g_cf[i * 64 + t];
    g_H4v[t] = acc;
}

// ---------------- head ----------------
__global__ __launch_bounds__(256) void x4_k()
{
    int i = blockIdx.x, t = threadIdx.x;
    float* row = g_X4 + i * 385;
    row[t] = g_H1[i * 256 + t];
    if (t < 64) {
        row[256 + t] = g_H2v[t];
        row[320 + t] = g_H3[i * 64 + t];
    }
    if (t == 0) row[384] = (i < 64) ? g_H4v[i] : 0.f;
}

__global__ __launch_bounds__(256) void ln_k(float* __restrict__ out,
                                            const float* __restrict__ ln_g, const float* __restrict__ ln_b)
{
    int i = blockIdx.x, t = threadIdx.x;
    __shared__ float red[256];
    float x = g_pre[i * 256 + t];
    red[t] = x; __syncthreads();
    for (int o = 128; o > 0; o >>= 1) { if (t < o) red[t] += red[t + o]; __syncthreads(); }
    float mu = red[0] * (1.f / 256.f);
    __syncthreads();
    float d = x - mu;
    red[t] = d * d; __syncthreads();
    for (int o = 128; o > 0; o >>= 1) { if (t < o) red[t] += red[t + o]; __syncthreads(); }
    float var = red[0] * (1.f / 256.f);
    float y = d * rsqrtf(var + 1e-5f) * ln_g[t] + ln_b[t];
    out[i * 256 + t] = (y > 0.f) ? y : expm1f(y);
}

// ---------------- host side ----------------
static void run_gemm_nt(const float* A, int lda, const float* B, int ldb,
                        float* dst, int M, int N, int K, const float* bias, int act)
{
    int ks = (K + 3) / 4;
    dim3 grid(N / 64, M / 64, 4);
    gemm_nt_k<<<grid, 256>>>(A, lda, B, ldb, M, N, K, ks);
    int MN = M * N;
    finish_k<<<(MN + 255) / 256, 256>>>(dst, MN, N - 1, bias, act);
}

extern "C" void kernel_launch(void* const* d_in, const int* in_sizes, int n_in,
                              void* d_out, int out_size)
{
    const float* V       = (const float*)d_in[0];
    const int*   adj     = (const int*)d_in[1];
    const float* prev    = (const float*)d_in[2];
    const float* W1      = (const float*)d_in[3];
    const float* sa0     = (const float*)d_in[4];
    const float* sa1     = (const float*)d_in[5];
    const float* ce_w1   = (const float*)d_in[6];
    const float* ce_b1   = (const float*)d_in[7];
    const float* ce_w2   = (const float*)d_in[8];
    const float* ce_b2   = (const float*)d_in[9];
    const float* ca0     = (const float*)d_in[10];
    const float* ca1     = (const float*)d_in[11];
    const float* te_w1   = (const float*)d_in[12];
    const float* te_b1   = (const float*)d_in[13];
    const float* te_w2   = (const float*)d_in[14];
    const float* te_b2   = (const float*)d_in[15];
    const float* pe_w1   = (const float*)d_in[18];
    const float* pe_b1   = (const float*)d_in[19];
    const float* pe_w2   = (const float*)d_in[20];
    const float* pe_b2   = (const float*)d_in[21];
    const float* W2      = (const float*)d_in[24];
    const float* op_w    = (const float*)d_in[25];
    const float* op_b    = (const float*)d_in[26];
    const float* ln_g    = (const float*)d_in[27];
    const float* ln_b    = (const float*)d_in[28];
    float* out = (float*)d_out;

    float *pWh1, *pH1, *pAr, *pBr, *pX2, *pHid, *pTf, *pX3, *pCf, *pX4, *pZ, *pPre, *pP;
    cudaGetSymbolAddress((void**)&pWh1, g_Wh1);
    cudaGetSymbolAddress((void**)&pH1,  g_H1);
    cudaGetSymbolAddress((void**)&pAr,  g_Ar);
    cudaGetSymbolAddress((void**)&pBr,  g_Br);
    cudaGetSymbolAddress((void**)&pX2,  g_X2);
    cudaGetSymbolAddress((void**)&pHid, g_hid);
    cudaGetSymbolAddress((void**)&pTf,  g_tf);
    cudaGetSymbolAddress((void**)&pX3,  g_X3);
    cudaGetSymbolAddress((void**)&pCf,  g_cf);
    cudaGetSymbolAddress((void**)&pX4,  g_X4);
    cudaGetSymbolAddress((void**)&pZ,   g_Z);
    cudaGetSymbolAddress((void**)&pPre, g_pre);
    cudaGetSymbolAddress((void**)&pP,   g_P);

    // --- GAT branch ---
    run_gemm_nt(V, 256, W1, 256, pWh1, 512, 256, 256, nullptr, 0);        // Wh1
    e01_k<<<128, 128>>>(sa0, sa1);
    gatP_k<<<512, 256>>>(adj);
    {   // H1 = P @ Wh1  (NN)
        dim3 grid(256 / 64, 512 / 64, 4);
        gemm_nn_k<<<grid, 256>>>(pP, 512, pWh1, 256, 512, 256, 512, 128);
        finish_k<<<(512 * 256 + 255) / 256, 256>>>(pH1, 512 * 256, 255, nullptr, 0);
    }

    // --- pair branch ---
    run_gemm_nt(V, 256, ce_w1, 512, pAr, 512, 256, 256, ce_b1, 0);        // A' = V@wA^T + b1
    run_gemm_nt(V, 256, ce_w1 + 256, 512, pBr, 512, 256, 256, nullptr, 0); // B = V@wB^T
    u_k<<<1, 256>>>(ce_w2, ca0, ca1);
    {
        dim3 grid(16, 8);
        pair_score_k<<<grid, 256>>>();
    }
    smax_part_k<<<256, 256>>>();
    smax_final_k<<<1, 256>>>();
    {
        dim3 grid(64, 2);
        pair_acc_k<<<grid, 256>>>();
    }
    gred_k<<<1, 256>>>();
    h2_k<<<64, 32>>>(ce_w2, ce_b2);

    // --- temporal branch ---
    concat2_k<<<512, 256>>>(V, prev);
    run_gemm_nt(pX2, 512, te_w1, 512, pHid, 512, 256, 512, te_b1, 1);
    run_gemm_nt(pHid, 256, te_w2, 256, pTf, 512, 64, 256, te_b2, 0);
    h3_k<<<1, 64>>>();

    // --- pair-encoder branch ---
    neigh_k<<<2, 256>>>(adj);
    concat3_k<<<512, 256>>>(V);
    run_gemm_nt(pX3, 768, pe_w1, 768, pHid, 512, 256, 768, pe_b1, 1);
    run_gemm_nt(pHid, 256, pe_w2, 256, pCf, 512, 64, 256, pe_b2, 0);
    h4_k<<<1, 64>>>();

    // --- head ---
    x4_k<<<512, 256>>>();
    run_gemm_nt(pX4, 385, W2, 385, pZ, 512, 256, 385, nullptr, 0);
    run_gemm_nt(pZ, 256, op_w, 256, pPre, 512, 256, 256, op_b, 0);
    ln_k<<<512, 256>>>(out, ln_g, ln_b);
}

// round 3
// speedup vs baseline: 1.1411x; 1.1411x over previous
#include <cuda_runtime.h>
#include <math.h>

#define NN 512
#define DF 256

// ---------------- scratch (device globals; no runtime alloc) ----------------
__device__ float g_Wh1[NN*DF];
__device__ float g_e0[NN], g_e1[NN];
__device__ float g_P[NN*NN];
__device__ float g_H1[NN*DF];
__device__ float g_Ar[NN*DF];
__device__ float g_Br[NN*DF];
__device__ float g_u[DF];
__device__ float g_red[256];
__device__ float g_MS[2];
__device__ float g_s2[NN*NN];
__device__ float g_part[128*DF];
__device__ float g_H2v[64];
__device__ float g_hidT[NN*DF];
__device__ float g_tf[NN*64];
__device__ float g_H3[NN*64];
__device__ int   g_i0[NN], g_i1[NN];
__device__ float g_hidP[NN*DF];
__device__ float g_cf[NN*64];
__device__ float g_H4v[64];
__device__ float g_Z[NN*DF];

// ---------------- generic 64x64 GEMM tile (dyn smem), A via loader ----------------
// BNN=false: C += A * B^T with B (N,K) row-major.  BNN=true: B is (K,N) row-major.
template <bool BNN, class AL>
__device__ __forceinline__ void gemm_tile(
    float* sm, AL aload, const float* __restrict__ B, int ldb, int K,
    int m0, int n0, float* __restrict__ C, int ldc,
    const float* __restrict__ bias, bool relu)
{
    float (*sA)[68] = (float(*)[68])sm;
    float (*sB)[68] = (float(*)[68])(sm + 16*68);
    int tid = threadIdx.x, tx = tid & 15, ty = tid >> 4;
    float acc[4][4] = {};
    for (int kc = 0; kc < K; kc += 16) {
#pragma unroll
        for (int s = 0; s < 4; s++) {
            int idx = tid + s * 256;
            int r = idx >> 4, k = idx & 15;
            int gk = kc + k;
            sA[k][r] = (gk < K) ? aload(m0 + r, gk) : 0.f;
            if (BNN) {
                int kb = idx >> 6, nb = idx & 63;
                int gkb = kc + kb;
                sB[kb][nb] = (gkb < K) ? B[gkb * ldb + n0 + nb] : 0.f;
            } else {
                sB[k][r] = (gk < K) ? B[(n0 + r) * ldb + gk] : 0.f;
            }
        }
        __syncthreads();
#pragma unroll
        for (int kk = 0; kk < 16; kk++) {
            float av[4], bv[4];
            *(float4*)av = *(const float4*)&sA[kk][ty << 2];
            *(float4*)bv = *(const float4*)&sB[kk][tx << 2];
#pragma unroll
            for (int i = 0; i < 4; i++)
#pragma unroll
                for (int j = 0; j < 4; j++)
                    acc[i][j] = fmaf(av[i], bv[j], acc[i][j]);
        }
        __syncthreads();
    }
#pragma unroll
    for (int i = 0; i < 4; i++)
#pragma unroll
        for (int j = 0; j < 4; j++) {
            int gm = m0 + ty * 4 + i, gn = n0 + tx * 4 + j;
            float v = acc[i][j];
            if (bias) v += bias[gn];
            if (relu) v = fmaxf(v, 0.f);
            C[gm * ldc + gn] = v;
        }
}

// ---------------- phase 0: neighbor indices + u vector ----------------
__global__ __launch_bounds__(256) void prep_k(const int* __restrict__ adj,
                                              const float* __restrict__ ce_w2,
                                              const float* __restrict__ ca0,
                                              const float* __restrict__ ca1)
{
    int b = blockIdx.x, tid = threadIdx.x;
    if (b < 2) {
        int i = b * 256 + tid;
        int a = NN, c = NN;
        for (int j = 0; j < NN; j++) {
            if (adj[i * NN + j] == 1) {
                if (a == NN) a = j;
                else { c = j; break; }
            }
        }
        g_i0[i] = a; g_i1[i] = c;
    } else {
        __shared__ float sc[64];
        if (tid < 64) sc[tid] = ca0[tid] + ca1[tid];
        __syncthreads();
        float acc = 0.f;
#pragma unroll 8
        for (int d = 0; d < 64; d++) acc += ce_w2[d * 256 + tid] * sc[d];
        g_u[tid] = acc;
    }
}

// ---------------- phase A: 5 fused first-layer GEMMs (160 blocks) ----------------
__global__ __launch_bounds__(256) void phaseA_k(
    const float* __restrict__ V, const float* __restrict__ prev,
    const float* __restrict__ W1,
    const float* __restrict__ ce_w1, const float* __restrict__ ce_b1,
    const float* __restrict__ te_w1, const float* __restrict__ te_b1,
    const float* __restrict__ pe_w1, const float* __restrict__ pe_b1)
{
    extern __shared__ float sm[];
    int b = blockIdx.x;
    auto ldV = [&](int i, int k) { return V[i * 256 + k]; };
    if (b < 32) {
        gemm_tile<false>(sm, ldV, W1, 256, 256, (b >> 2) * 64, (b & 3) * 64, g_Wh1, 256, nullptr, false);
    } else if (b < 64) {
        b -= 32;
        gemm_tile<false>(sm, ldV, ce_w1, 512, 256, (b >> 2) * 64, (b & 3) * 64, g_Ar, 256, ce_b1, false);
    } else if (b < 96) {
        b -= 64;
        gemm_tile<false>(sm, ldV, ce_w1 + 256, 512, 256, (b >> 2) * 64, (b & 3) * 64, g_Br, 256, nullptr, false);
    } else if (b < 128) {
        b -= 96;
        auto ld2 = [&](int i, int k) { return (k < 256) ? V[i * 256 + k] : prev[i * 256 + k - 256]; };
        gemm_tile<false>(sm, ld2, te_w1, 512, 512, (b >> 2) * 64, (b & 3) * 64, g_hidT, 256, te_b1, true);
    } else {
        b -= 128;
        auto ld3 = [&](int i, int k) {
            if (k < 256) return V[i * 256 + k];
            int i1 = g_i1[i];
            if (i1 >= NN) return 0.f;
            if (k < 512) return V[min(g_i0[i], NN - 1) * 256 + (k - 256)];
            return V[min(i1, NN - 1) * 256 + (k - 512)];
        };
        gemm_tile<false>(sm, ld3, pe_w1, 768, 768, (b >> 2) * 64, (b & 3) * 64, g_hidP, 256, pe_b1, true);
    }
}

// ---------------- phase 2a: e01 + tf + cf + pair_score (208 blocks) ----------------
__global__ __launch_bounds__(256) void phase2a_k(
    const float* __restrict__ sa0, const float* __restrict__ sa1,
    const float* __restrict__ te_w2, const float* __restrict__ te_b2,
    const float* __restrict__ pe_w2, const float* __restrict__ pe_b2)
{
    extern __shared__ float sm[];
    int b = blockIdx.x, tid = threadIdx.x;
    if (b < 64) {
        // e0/e1: 8 rows per block
        int w = tid >> 5, lane = tid & 31;
        int row = b * 8 + w;
        float a0 = 0.f, a1 = 0.f;
#pragma unroll
        for (int l = 0; l < 8; l++) {
            int k = lane + l * 32;
            float a = g_Wh1[row * 256 + k];
            a0 += a * sa0[k];
            a1 += a * sa1[k];
        }
#pragma unroll
        for (int o = 16; o > 0; o >>= 1) {
            a0 += __shfl_down_sync(0xffffffffu, a0, o);
            a1 += __shfl_down_sync(0xffffffffu, a1, o);
        }
        if (lane == 0) { g_e0[row] = a0; g_e1[row] = a1; }
    } else if (b < 72) {
        auto ld = [&](int i, int k) { return g_hidT[i * 256 + k]; };
        gemm_tile<false>(sm, ld, te_w2, 256, 256, (b - 64) * 64, 0, g_tf, 64, te_b2, false);
    } else if (b < 80) {
        auto ld = [&](int i, int k) { return g_hidP[i * 256 + k]; };
        gemm_tile<false>(sm, ld, pe_w2, 256, 256, (b - 72) * 64, 0, g_cf, 64, pe_b2, false);
    } else {
        // pair_score: s2[i,j] = sum_k relu(Ar+Br)*u; + online (m,s) partial
        int pb = b - 80;
        int ib = (pb >> 4) * 64, jb = (pb & 15) * 32;
        float (*sA)[68] = (float(*)[68])sm;
        float (*sB)[36] = (float(*)[36])(sm + 16 * 68);
        float* su = sm + 16 * 68 + 16 * 36;
        float* rm = su + 16;
        float* rs = rm + 256;
        int tx = tid & 15, ty = tid >> 4;
        float acc[4][2] = {};
        for (int kc = 0; kc < 256; kc += 16) {
#pragma unroll
            for (int s = 0; s < 4; s++) {
                int idx = tid + s * 256;
                int r = idx >> 4, k = idx & 15;
                sA[k][r] = g_Ar[(ib + r) * 256 + kc + k];
            }
#pragma unroll
            for (int s = 0; s < 2; s++) {
                int idx = tid + s * 256;
                int r = idx >> 4, k = idx & 15;
                sB[k][r] = g_Br[(jb + r) * 256 + kc + k];
            }
            if (tid < 16) su[tid] = g_u[kc + tid];
            __syncthreads();
#pragma unroll
            for (int kk = 0; kk < 16; kk++) {
                float av[4], bv[2];
                *(float4*)av = *(const float4*)&sA[kk][ty << 2];
                *(float2*)bv = *(const float2*)&sB[kk][tx << 1];
                float uu = su[kk];
#pragma unroll
                for (int i = 0; i < 4; i++)
#pragma unroll
                    for (int j = 0; j < 2; j++)
                        acc[i][j] += fmaxf(av[i] + bv[j], 0.f) * uu;
            }
            __syncthreads();
        }
        float m = -3.402823466e38f, sum = 0.f;
#pragma unroll
        for (int i = 0; i < 4; i++)
#pragma unroll
            for (int j = 0; j < 2; j++) {
                int gi = ib + ty * 4 + i, gj = jb + tx * 2 + j;
                float v = (gi == gj) ? -INFINITY : acc[i][j];
                g_s2[gi * NN + gj] = v;
                float nm = fmaxf(m, v);
                sum = sum * expf(m - nm) + expf(v - nm);
                m = nm;
            }
        rm[tid] = m; rs[tid] = sum; __syncthreads();
        for (int o = 128; o > 0; o >>= 1) {
            if (tid < o) {
                float m2 = rm[tid + o], s2v = rs[tid + o];
                float M = fmaxf(rm[tid], m2);
                rs[tid] = rs[tid] * expf(rm[tid] - M) + s2v * expf(m2 - M);
                rm[tid] = M;
            }
            __syncthreads();
        }
        if (tid == 0) { g_red[2 * pb] = rm[0]; g_red[2 * pb + 1] = rs[0]; }
    }
}

// ---------------- phase 2b: smax_final + h3 + h4 + gatP (515 blocks) ----------------
__global__ __launch_bounds__(256) void phase2b_k(const int* __restrict__ adj)
{
    __shared__ float r1[256], r2[256];
    int b = blockIdx.x, tid = threadIdx.x;
    if (b == 0) {
        float m = (tid < 128) ? g_red[2 * tid] : -INFINITY;
        float s = (tid < 128) ? g_red[2 * tid + 1] : 0.f;
        r1[tid] = m; r2[tid] = s; __syncthreads();
        for (int o = 128; o > 0; o >>= 1) {
            if (tid < o) {
                float m2 = r1[tid + o], s2v = r2[tid + o];
                float M = fmaxf(r1[tid], m2);
                r2[tid] = r2[tid] * expf(r1[tid] - M) + s2v * expf(m2 - M);
                r1[tid] = M;
            }
            __syncthreads();
        }
        if (tid == 0) { g_MS[0] = r1[0]; g_MS[1] = r2[0]; }
    } else if (b == 1) {
        // H3: prefix mean of tf, 4 segments of 128
        int t = tid & 63, s = tid >> 6;
        float acc = 0.f;
        for (int i = s * 128; i < s * 128 + 128; i++) acc += g_tf[i * 64 + t];
        r1[s * 64 + t] = acc; __syncthreads();
        float off = 0.f;
        for (int q = 0; q < s; q++) off += r1[q * 64 + t];
        acc = off;
        for (int i = s * 128; i < s * 128 + 128; i++) {
            acc += g_tf[i * 64 + t];
            g_H3[i * 64 + t] = acc / (float)(i + 1);
        }
    } else if (b == 2) {
        int t = tid & 63, s = tid >> 6;
        float acc = 0.f;
        for (int i = s * 128; i < s * 128 + 128; i++) acc += g_cf[i * 64 + t];
        r1[s * 64 + t] = acc; __syncthreads();
        if (s == 0) g_H4v[t] = r1[t] + r1[64 + t] + r1[128 + t] + r1[192 + t];
    } else {
        int i = b - 3;
        float e0i = g_e0[i];
        float sl[2];
        float m = -3.402823466e38f;
#pragma unroll
        for (int s = 0; s < 2; s++) {
            int j = tid + s * 256;
            float v = (adj[i * NN + j] != 0) ? (e0i + g_e1[j]) : -INFINITY;
            sl[s] = v;
            m = fmaxf(m, v);
        }
        r1[tid] = m; __syncthreads();
        for (int o = 128; o > 0; o >>= 1) { if (tid < o) r1[tid] = fmaxf(r1[tid], r1[tid + o]); __syncthreads(); }
        m = r1[0]; __syncthreads();
        float e[2]; float sum = 0.f;
#pragma unroll
        for (int s = 0; s < 2; s++) { e[s] = expf(sl[s] - m); sum += e[s]; }
        r1[tid] = sum; __syncthreads();
        for (int o = 128; o > 0; o >>= 1) { if (tid < o) r1[tid] += r1[tid + o]; __syncthreads(); }
        float inv = 1.f / r1[0];
#pragma unroll
        for (int s = 0; s < 2; s++) g_P[i * NN + tid + s * 256] = e[s] * inv;
    }
}

// ---------------- phase 2c: H1 GEMM + pair_acc (160 blocks) ----------------
__global__ __launch_bounds__(256) void phase2c_k()
{
    extern __shared__ float sm[];
    int b = blockIdx.x, tid = threadIdx.x;
    if (b < 32) {
        auto ld = [&](int i, int k) { return g_P[i * 512 + k]; };
        gemm_tile<true>(sm, ld, g_Wh1, 256, 512, (b >> 2) * 64, (b & 3) * 64, g_H1, 256, nullptr, false);
    } else {
        int pb = b - 32;
        int i0 = (pb & 63) * 8;
        int jb = (pb >> 6) * 256;
        float M = g_MS[0], invS = 1.f / g_MS[1];
        float a[8];
#pragma unroll
        for (int ii = 0; ii < 8; ii++) a[ii] = g_Ar[(i0 + ii) * 256 + tid];
        float acc = 0.f;
        float* sw = sm;  // [8][32]
        int li = tid >> 5, lj = tid & 31;
        for (int jc = jb; jc < jb + 256; jc += 32) {
            sw[li * 32 + lj] = expf(g_s2[(i0 + li) * NN + jc + lj] - M) * invS;
            __syncthreads();
#pragma unroll 4
            for (int jj = 0; jj < 32; jj++) {
                float bb = g_Br[(jc + jj) * 256 + tid];
#pragma unroll
                for (int ii = 0; ii < 8; ii++)
                    acc += sw[ii * 32 + jj] * fmaxf(a[ii] + bb, 0.f);
            }
            __syncthreads();
        }
        g_part[((pb >> 6) * 64 + (pb & 63)) * 256 + tid] = acc;
    }
}

// ---------------- phase 2d: H2v (gred folded in, 64 blocks) ----------------
__global__ __launch_bounds__(256) void h2f_k(const float* __restrict__ ce_w2,
                                             const float* __restrict__ ce_b2)
{
    __shared__ float red[256];
    int d = blockIdx.x, tid = threadIdx.x;
    float gv = 0.f;
#pragma unroll 8
    for (int b2 = 0; b2 < 128; b2++) gv += g_part[b2 * 256 + tid];
    red[tid] = gv * ce_w2[d * 256 + tid];
    __syncthreads();
    for (int o = 128; o > 0; o >>= 1) { if (tid < o) red[tid] += red[tid + o]; __syncthreads(); }
    if (tid == 0) g_H2v[d] = red[0] + ce_b2[d];
}

// ---------------- phase 3: Z = [H1|H2v|H3|H4col] @ W2^T (gather A) ----------------
__global__ __launch_bounds__(256) void phaseZ_k(const float* __restrict__ W2)
{
    extern __shared__ float sm[];
    int b = blockIdx.x;
    auto ld = [&](int i, int k) {
        if (k < 256) return g_H1[i * 256 + k];
        if (k < 320) return g_H2v[k - 256];
        if (k < 384) return g_H3[i * 64 + (k - 320)];
        return (i < 64) ? g_H4v[i] : 0.f;
    };
    gemm_tile<false>(sm, ld, W2, 385, 385, (b >> 2) * 64, (b & 3) * 64, g_Z, 256, nullptr, false);
}

// ---------------- phase 4: op GEMM fused with LayerNorm+ELU ----------------
// 16 blocks, 32 rows x 256 cols per block, micro 2x16
__global__ __launch_bounds__(256) void opln_k(const float* __restrict__ op_w,
                                              const float* __restrict__ op_b,
                                              const float* __restrict__ ln_g,
                                              const float* __restrict__ ln_b,
                                              float* __restrict__ out)
{
    __shared__ float sA[16][34];
    __shared__ float sB[16][257];
    int tid = threadIdx.x, tx = tid & 15, ty = tid >> 4;
    int m0 = blockIdx.x * 32;
    float acc[2][16] = {};
    for (int kc = 0; kc < 256; kc += 16) {
#pragma unroll
        for (int s = 0; s < 2; s++) {
            int idx = tid + s * 256;
            int r = idx >> 4, k = idx & 15;
            sA[k][r] = g_Z[(m0 + r) * 256 + kc + k];
        }
#pragma unroll
        for (int s = 0; s < 16; s++) {
            int idx = tid + s * 256;
            int k = idx & 15, n = idx >> 4;
            sB[k][n] = op_w[n * 256 + kc + k];
        }
        __syncthreads();
#pragma unroll
        for (int kk = 0; kk < 16; kk++) {
            float av0 = sA[kk][ty * 2], av1 = sA[kk][ty * 2 + 1];
#pragma unroll
            for (int j = 0; j < 16; j++) {
                float bv = sB[kk][tx + 16 * j];
                acc[0][j] = fmaf(av0, bv, acc[0][j]);
                acc[1][j] = fmaf(av1, bv, acc[1][j]);
            }
        }
        __syncthreads();
    }
#pragma unroll
    for (int i = 0; i < 2; i++) {
        float rsum = 0.f;
#pragma unroll
        for (int j = 0; j < 16; j++) {
            acc[i][j] += op_b[tx + 16 * j];
            rsum += acc[i][j];
        }
#pragma unroll
        for (int o = 1; o < 16; o <<= 1) rsum += __shfl_xor_sync(0xffffffffu, rsum, o);
        float mu = rsum * (1.f / 256.f);
        float vsum = 0.f;
#pragma unroll
        for (int j = 0; j < 16; j++) { float d = acc[i][j] - mu; vsum += d * d; }
#pragma unroll
        for (int o = 1; o < 16; o <<= 1) vsum += __shfl_xor_sync(0xffffffffu, vsum, o);
        float inv = rsqrtf(vsum * (1.f / 256.f) + 1e-5f);
        int gm = m0 + ty * 2 + i;
#pragma unroll
        for (int j = 0; j < 16; j++) {
            int n = tx + 16 * j;
            float y = (acc[i][j] - mu) * inv * ln_g[n] + ln_b[n];
            out[gm * 256 + n] = (y > 0.f) ? y : expm1f(y);
        }
    }
}

// ---------------- host side ----------------
extern "C" void kernel_launch(void* const* d_in, const int* in_sizes, int n_in,
                              void* d_out, int out_size)
{
    const float* V       = (const float*)d_in[0];
    const int*   adj     = (const int*)d_in[1];
    const float* prev    = (const float*)d_in[2];
    const float* W1      = (const float*)d_in[3];
    const float* sa0     = (const float*)d_in[4];
    const float* sa1     = (const float*)d_in[5];
    const float* ce_w1   = (const float*)d_in[6];
    const float* ce_b1   = (const float*)d_in[7];
    const float* ce_w2   = (const float*)d_in[8];
    const float* ce_b2   = (const float*)d_in[9];
    const float* ca0     = (const float*)d_in[10];
    const float* ca1     = (const float*)d_in[11];
    const float* te_w1   = (const float*)d_in[12];
    const float* te_b1   = (const float*)d_in[13];
    const float* te_w2   = (const float*)d_in[14];
    const float* te_b2   = (const float*)d_in[15];
    const float* pe_w1   = (const float*)d_in[18];
    const float* pe_b1   = (const float*)d_in[19];
    const float* pe_w2   = (const float*)d_in[20];
    const float* pe_b2   = (const float*)d_in[21];
    const float* W2      = (const float*)d_in[24];
    const float* op_w    = (const float*)d_in[25];
    const float* op_b    = (const float*)d_in[26];
    const float* ln_g    = (const float*)d_in[27];
    const float* ln_b    = (const float*)d_in[28];
    float* out = (float*)d_out;

    const int GSM = 16 * 68 * 2 * 4;      // 8704B generic gemm tile
    const int PSM = (16*68 + 16*36 + 16 + 512) * 4;  // 8768B pair_score

    prep_k   <<<3,   256>>>(adj, ce_w2, ca0, ca1);
    phaseA_k <<<160, 256, GSM>>>(V, prev, W1, ce_w1, ce_b1, te_w1, te_b1, pe_w1, pe_b1);
    phase2a_k<<<208, 256, PSM>>>(sa0, sa1, te_w2, te_b2, pe_w2, pe_b2);
    phase2b_k<<<515, 256>>>(adj);
    phase2c_k<<<160, 256, GSM>>>();
    h2f_k    <<<64,  256>>>(ce_w2, ce_b2);
    phaseZ_k <<<32,  256, GSM>>>(W2);
    opln_k   <<<16,  256>>>(op_w, op_b, ln_g, ln_b, out);
}

// round 4
// speedup vs baseline: 1.4174x; 1.2421x over previous
#include <cuda_runtime.h>
#include <math.h>

#define NN 512
#define DF 256

// ---------------- scratch (device globals) ----------------
// split-K slabs (raw GEMM chunk outputs)
__device__ float g_Wh1s[2][NN*DF];
__device__ float g_Ars[2][NN*DF];
__device__ float g_Brs[2][NN*DF];
__device__ float g_hidTs[4][NN*DF];
__device__ float g_hidPs[6][NN*DF];
__device__ float g_tfs[2][NN*64];
__device__ float g_cfs[2][NN*64];
__device__ float g_H1s[4][NN*DF];
__device__ float g_Zs[3][NN*DF];
// materialized tensors
__device__ float g_Wh1F[NN*DF];
__device__ float g_ArF[NN*DF];
__device__ float g_BrF[NN*DF];
__device__ float g_e0[NN], g_e1[NN];
__device__ float g_P[NN*NN];
__device__ float g_u[DF];
__device__ float g_red[1024];
__device__ float g_MS[2];
__device__ float g_s2[NN*NN];
__device__ float g_part[512*DF];
__device__ float g_H2v[64];
__device__ float g_H3[NN*64];
__device__ int   g_i0[NN], g_i1[NN];
__device__ float g_H4v[64];

// ---------------- 64x64 GEMM tile over K range [K0,K1), raw output ----------------
// BNN=false: B is (N,K) row-major (nt). BNN=true: B is (K,N) row-major (nn).
template <bool BNN, class AL>
__device__ __forceinline__ void gemm64(
    float* sm, AL aload, const float* __restrict__ B, int ldb,
    int K0, int K1, int m0, int n0, float* __restrict__ C, int ldc)
{
    float (*sA)[68] = (float(*)[68])sm;
    float (*sB)[68] = (float(*)[68])(sm + 16*68);
    int tid = threadIdx.x, tx = tid & 15, ty = tid >> 4;
    float acc[4][4] = {};
    for (int kc = K0; kc < K1; kc += 16) {
#pragma unroll
        for (int s = 0; s < 4; s++) {
            int idx = tid + s * 256;
            int r = idx >> 4, k = idx & 15;
            int gk = kc + k;
            sA[k][r] = (gk < K1) ? aload(m0 + r, gk) : 0.f;
            if (BNN) {
                int kb = idx >> 6, nb = idx & 63;
                int gkb = kc + kb;
                sB[kb][nb] = (gkb < K1) ? B[gkb * ldb + n0 + nb] : 0.f;
            } else {
                sB[k][r] = (gk < K1) ? B[(n0 + r) * ldb + gk] : 0.f;
            }
        }
        __syncthreads();
#pragma unroll
        for (int kk = 0; kk < 16; kk++) {
            float av[4], bv[4];
            *(float4*)av = *(const float4*)&sA[kk][ty << 2];
            *(float4*)bv = *(const float4*)&sB[kk][tx << 2];
#pragma unroll
            for (int i = 0; i < 4; i++)
#pragma unroll
                for (int j = 0; j < 4; j++)
                    acc[i][j] = fmaf(av[i], bv[j], acc[i][j]);
        }
        __syncthreads();
    }
#pragma unroll
    for (int i = 0; i < 4; i++)
#pragma unroll
        for (int j = 0; j < 4; j++)
            C[(m0 + ty * 4 + i) * ldc + (n0 + tx * 4 + j)] = acc[i][j];
}

// ---------------- prep: neighbor indices + u ----------------
__global__ __launch_bounds__(256) void prep_k(const int* __restrict__ adj,
                                              const float* __restrict__ ce_w2,
                                              const float* __restrict__ ca0,
                                              const float* __restrict__ ca1)
{
    int b = blockIdx.x, tid = threadIdx.x;
    if (b < 2) {
        int i = b * 256 + tid;
        int a = NN, c = NN;
        for (int j = 0; j < NN; j++) {
            if (adj[i * NN + j] == 1) {
                if (a == NN) a = j;
                else { c = j; break; }
            }
        }
        g_i0[i] = a; g_i1[i] = c;
    } else {
        __shared__ float sc[64];
        if (tid < 64) sc[tid] = ca0[tid] + ca1[tid];
        __syncthreads();
        float acc = 0.f;
#pragma unroll 8
        for (int d = 0; d < 64; d++) acc += ce_w2[d * 256 + tid] * sc[d];
        g_u[tid] = acc;
    }
}

// ---------------- phase A: first-layer GEMMs, split-K chunks (512 blocks) ----------------
__global__ __launch_bounds__(256) void phaseA_k(
    const float* __restrict__ V, const float* __restrict__ prev,
    const float* __restrict__ W1,
    const float* __restrict__ ce_w1,
    const float* __restrict__ te_w1,
    const float* __restrict__ pe_w1)
{
    extern __shared__ float sm[];
    int b = blockIdx.x;
    auto ldV = [&](int i, int k) { return V[i * 256 + k]; };
    if (b < 64) {          // Wh1: 32 tiles x 2 chunks
        int c = b >> 5, t = b & 31;
        gemm64<false>(sm, ldV, W1, 256, c * 128, c * 128 + 128,
                      (t >> 2) * 64, (t & 3) * 64, g_Wh1s[c], 256);
    } else if (b < 128) {  // Ar
        b -= 64; int c = b >> 5, t = b & 31;
        gemm64<false>(sm, ldV, ce_w1, 512, c * 128, c * 128 + 128,
                      (t >> 2) * 64, (t & 3) * 64, g_Ars[c], 256);
    } else if (b < 192) {  // Br
        b -= 128; int c = b >> 5, t = b & 31;
        gemm64<false>(sm, ldV, ce_w1 + 256, 512, c * 128, c * 128 + 128,
                      (t >> 2) * 64, (t & 3) * 64, g_Brs[c], 256);
    } else if (b < 320) {  // hidT: K=512 -> 4 chunks
        b -= 192; int c = b >> 5, t = b & 31;
        auto ld2 = [&](int i, int k) { return (k < 256) ? V[i * 256 + k] : prev[i * 256 + k - 256]; };
        gemm64<false>(sm, ld2, te_w1, 512, c * 128, c * 128 + 128,
                      (t >> 2) * 64, (t & 3) * 64, g_hidTs[c], 256);
    } else {               // hidP: K=768 -> 6 chunks
        b -= 320; int c = b >> 5, t = b & 31;
        auto ld3 = [&](int i, int k) {
            if (k < 256) return V[i * 256 + k];
            int i1 = g_i1[i];
            if (i1 >= NN) return 0.f;
            if (k < 512) return V[min(g_i0[i], NN - 1) * 256 + (k - 256)];
            return V[min(i1, NN - 1) * 256 + (k - 512)];
        };
        gemm64<false>(sm, ld3, pe_w1, 768, c * 128, c * 128 + 128,
                      (t >> 2) * 64, (t & 3) * 64, g_hidPs[c], 256);
    }
}

// ---------------- phase 2a: pair_score + e01 + tf + cf + finish (656 blocks) ----------------
__global__ __launch_bounds__(256) void phase2a_k(
    const float* __restrict__ sa0, const float* __restrict__ sa1,
    const float* __restrict__ ce_b1,
    const float* __restrict__ te_w2, const float* __restrict__ te_b1,
    const float* __restrict__ pe_w2, const float* __restrict__ pe_b1)
{
    extern __shared__ float sm[];
    int b = blockIdx.x, tid = threadIdx.x;
    if (b < 512) {
        // pair_score: 32i x 16j tile, full K=256, online (m,s) epilogue
        float (*sA)[34] = (float(*)[34])sm;                    // [16][34]
        float (*sB)[18] = (float(*)[18])(sm + 16 * 34);        // [16][18]
        float* su = sm + 16 * 34 + 16 * 18;
        float* rm = su + 16;
        float* rs = rm + 256;
        int tx = tid & 15, ty = tid >> 4;
        int ib = (b >> 5) * 32, jb = (b & 31) * 16;
        float acc0 = 0.f, acc1 = 0.f;
        for (int kc = 0; kc < 256; kc += 16) {
#pragma unroll
            for (int s = 0; s < 2; s++) {
                int idx = tid + s * 256;
                int r = idx >> 4, k = idx & 15;
                int gi = (ib + r) * 256 + kc + k;
                sA[k][r] = g_Ars[0][gi] + g_Ars[1][gi] + ce_b1[kc + k];
            }
            {
                int r = tid >> 4, k = tid & 15;
                int gj = (jb + r) * 256 + kc + k;
                sB[k][r] = g_Brs[0][gj] + g_Brs[1][gj];
            }
            if (tid < 16) su[tid] = g_u[kc + tid];
            __syncthreads();
            float uu[16];
#pragma unroll
            for (int l = 0; l < 16; l++) uu[l] = su[l];
#pragma unroll
            for (int kk = 0; kk < 16; kk++) {
                float2 a = *(const float2*)&sA[kk][ty * 2];
                float bb = sB[kk][tx];
                acc0 += fmaxf(a.x + bb, 0.f) * uu[kk];
                acc1 += fmaxf(a.y + bb, 0.f) * uu[kk];
            }
            __syncthreads();
        }
        int gi0 = ib + ty * 2, gi1 = gi0 + 1, gj = jb + tx;
        float v0 = (gi0 == gj) ? -INFINITY : acc0;
        float v1 = (gi1 == gj) ? -INFINITY : acc1;
        g_s2[gi0 * NN + gj] = v0;
        g_s2[gi1 * NN + gj] = v1;
        float m = fmaxf(v0, v1);
        float sum = expf(v0 - m) + expf(v1 - m);
        rm[tid] = m; rs[tid] = sum; __syncthreads();
        for (int o = 128; o > 0; o >>= 1) {
            if (tid < o) {
                float m2 = rm[tid + o], s2v = rs[tid + o];
                float M = fmaxf(rm[tid], m2);
                rs[tid] = rs[tid] * expf(rm[tid] - M) + s2v * expf(m2 - M);
                rm[tid] = M;
            }
            __syncthreads();
        }
        if (tid == 0) { g_red[2 * b] = rm[0]; g_red[2 * b + 1] = rs[0]; }
    } else if (b < 576) {
        // e01: 8 rows per block (fold Wh1 slabs)
        int eb = b - 512;
        int w = tid >> 5, lane = tid & 31;
        int row = eb * 8 + w;
        float a0 = 0.f, a1 = 0.f;
#pragma unroll
        for (int l = 0; l < 8; l++) {
            int k = lane + l * 32;
            float a = g_Wh1s[0][row * 256 + k] + g_Wh1s[1][row * 256 + k];
            a0 += a * sa0[k];
            a1 += a * sa1[k];
        }
#pragma unroll
        for (int o = 16; o > 0; o >>= 1) {
            a0 += __shfl_down_sync(0xffffffffu, a0, o);
            a1 += __shfl_down_sync(0xffffffffu, a1, o);
        }
        if (lane == 0) { g_e0[row] = a0; g_e1[row] = a1; }
    } else if (b < 592) {
        // tf = relu(hidT) @ te_w2^T chunks (fold 4 slabs + te_b1 + relu)
        int t = b - 576; int c = t >> 3, mt = t & 7;
        auto ld = [&](int i, int k) {
            int g = i * 256 + k;
            return fmaxf(g_hidTs[0][g] + g_hidTs[1][g] + g_hidTs[2][g] + g_hidTs[3][g] + te_b1[k], 0.f);
        };
        gemm64<false>(sm, ld, te_w2, 256, c * 128, c * 128 + 128, mt * 64, 0, g_tfs[c], 64);
    } else if (b < 608) {
        int t = b - 592; int c = t >> 3, mt = t & 7;
        auto ld = [&](int i, int k) {
            int g = i * 256 + k;
            return fmaxf(g_hidPs[0][g] + g_hidPs[1][g] + g_hidPs[2][g] + g_hidPs[3][g]
                         + g_hidPs[4][g] + g_hidPs[5][g] + pe_b1[k], 0.f);
        };
        gemm64<false>(sm, ld, pe_w2, 256, c * 128, c * 128 + 128, mt * 64, 0, g_cfs[c], 64);
    } else {
        // finish: materialize Wh1F / ArF / BrF (48 blocks, 32 rows each)
        int fb = b - 608;
        int tens = fb >> 4, sub = fb & 15;
        int base = sub * 8192;
#pragma unroll 4
        for (int j = 0; j < 32; j++) {
            int idx = base + j * 256 + tid;
            if (tens == 0) g_Wh1F[idx] = g_Wh1s[0][idx] + g_Wh1s[1][idx];
            else if (tens == 1) g_ArF[idx] = g_Ars[0][idx] + g_Ars[1][idx] + ce_b1[tid];
            else g_BrF[idx] = g_Brs[0][idx] + g_Brs[1][idx];
        }
    }
}

// ---------------- phase 2b: smax_final + H3 + H4 + gatP (515 blocks) ----------------
__global__ __launch_bounds__(256) void phase2b_k(const int* __restrict__ adj,
                                                 const float* __restrict__ te_b2,
                                                 const float* __restrict__ pe_b2)
{
    __shared__ float r1[256], r2[256];
    int b = blockIdx.x, tid = threadIdx.x;
    if (b == 0) {
        // combine 512 (m,s) partials
        float ma = g_red[2 * tid],       sa = g_red[2 * tid + 1];
        float mb = g_red[2 * (tid+256)], sb = g_red[2 * (tid+256) + 1];
        float M = fmaxf(ma, mb);
        float S = sa * expf(ma - M) + sb * expf(mb - M);
        r1[tid] = M; r2[tid] = S; __syncthreads();
        for (int o = 128; o > 0; o >>= 1) {
            if (tid < o) {
                float m2 = r1[tid + o], s2v = r2[tid + o];
                float MM = fmaxf(r1[tid], m2);
                r2[tid] = r2[tid] * expf(r1[tid] - MM) + s2v * expf(m2 - MM);
                r1[tid] = MM;
            }
            __syncthreads();
        }
        if (tid == 0) { g_MS[0] = r1[0]; g_MS[1] = r2[0]; }
    } else if (b == 1) {
        // H3 prefix mean: 64 channels x 4 segments of 128
        int t = tid & 63, s = tid >> 6;
        float bias = te_b2[t];
        int i0 = s * 128;
        float p0 = 0.f, p1 = 0.f, p2 = 0.f, p3 = 0.f;
#pragma unroll 8
        for (int i = i0; i < i0 + 128; i += 4) {
            p0 += g_tfs[0][i * 64 + t] + g_tfs[1][i * 64 + t];
            p1 += g_tfs[0][(i+1) * 64 + t] + g_tfs[1][(i+1) * 64 + t];
            p2 += g_tfs[0][(i+2) * 64 + t] + g_tfs[1][(i+2) * 64 + t];
            p3 += g_tfs[0][(i+3) * 64 + t] + g_tfs[1][(i+3) * 64 + t];
        }
        r1[s * 64 + t] = p0 + p1 + p2 + p3 + 128.f * bias;
        __syncthreads();
        float acc = 0.f;
        for (int q = 0; q < s; q++) acc += r1[q * 64 + t];
#pragma unroll 16
        for (int i = i0; i < i0 + 128; i++) {
            acc += g_tfs[0][i * 64 + t] + g_tfs[1][i * 64 + t] + bias;
            g_H3[i * 64 + t] = acc / (float)(i + 1);
        }
    } else if (b == 2) {
        // H4v: column sum of cf
        int t = tid & 63, s = tid >> 6;
        float bias = pe_b2[t];
        int i0 = s * 128;
        float p0 = 0.f, p1 = 0.f;
#pragma unroll 8
        for (int i = i0; i < i0 + 128; i += 2) {
            p0 += g_cfs[0][i * 64 + t] + g_cfs[1][i * 64 + t];
            p1 += g_cfs[0][(i+1) * 64 + t] + g_cfs[1][(i+1) * 64 + t];
        }
        r1[s * 64 + t] = p0 + p1 + 128.f * bias;
        __syncthreads();
        if (s == 0) g_H4v[t] = r1[t] + r1[64 + t] + r1[128 + t] + r1[192 + t];
    } else {
        // gatP row softmax
        int i = b - 3;
        float e0i = g_e0[i];
        float sl[2];
        float m = -3.402823466e38f;
#pragma unroll
        for (int s = 0; s < 2; s++) {
            int j = tid + s * 256;
            float v = (adj[i * NN + j] != 0) ? (e0i + g_e1[j]) : -INFINITY;
            sl[s] = v;
            m = fmaxf(m, v);
        }
        r1[tid] = m; __syncthreads();
        for (int o = 128; o > 0; o >>= 1) { if (tid < o) r1[tid] = fmaxf(r1[tid], r1[tid + o]); __syncthreads(); }
        m = r1[0]; __syncthreads();
        float e[2]; float sum = 0.f;
#pragma unroll
        for (int s = 0; s < 2; s++) { e[s] = expf(sl[s] - m); sum += e[s]; }
        r1[tid] = sum; __syncthreads();
        for (int o = 128; o > 0; o >>= 1) { if (tid < o) r1[tid] += r1[tid + o]; __syncthreads(); }
        float inv = 1.f / r1[0];
#pragma unroll
        for (int s = 0; s < 2; s++) g_P[i * NN + tid + s * 256] = e[s] * inv;
    }
}

// ---------------- phase 2c: H1 chunks + pair_acc (640 blocks) ----------------
__global__ __launch_bounds__(256) void phase2c_k()
{
    extern __shared__ float sm[];
    int b = blockIdx.x, tid = threadIdx.x;
    if (b < 128) {
        int c = b >> 5, t = b & 31;
        auto ld = [&](int i, int k) { return g_P[i * 512 + k]; };
        gemm64<true>(sm, ld, g_Wh1F, 256, c * 128, c * 128 + 128,
                     (t >> 2) * 64, (t & 3) * 64, g_H1s[c], 256);
    } else {
        int pb = b - 128;                // 512 blocks: 64 i-groups x 8 j-chunks of 64
        int i0 = (pb & 63) * 8;
        int jb = (pb >> 6) * 64;
        float M = g_MS[0], invS = 1.f / g_MS[1];
        float a[8];
#pragma unroll
        for (int ii = 0; ii < 8; ii++) a[ii] = g_ArF[(i0 + ii) * 256 + tid];
        float acc = 0.f;
        float* sw = sm;  // [8][32]
        int li = tid >> 5, lj = tid & 31;
        for (int jc = jb; jc < jb + 64; jc += 32) {
            sw[li * 32 + lj] = expf(g_s2[(i0 + li) * NN + jc + lj] - M) * invS;
            __syncthreads();
#pragma unroll 4
            for (int jj = 0; jj < 32; jj++) {
                float bb = g_BrF[(jc + jj) * 256 + tid];
#pragma unroll
                for (int ii = 0; ii < 8; ii++)
                    acc += sw[ii * 32 + jj] * fmaxf(a[ii] + bb, 0.f);
            }
            __syncthreads();
        }
        g_part[pb * 256 + tid] = acc;
    }
}

// ---------------- h2: gv colsum + H2v gemv (1 block) ----------------
__global__ __launch_bounds__(256) void h2_k(const float* __restrict__ ce_w2,
                                            const float* __restrict__ ce_b2)
{
    __shared__ float gv[256];
    __shared__ float red[256];
    int tid = threadIdx.x;
    float acc = 0.f;
#pragma unroll 8
    for (int r = 0; r < 512; r++) acc += g_part[r * 256 + tid];
    gv[tid] = acc;
    __syncthreads();
    int d = tid >> 2, q = tid & 3;       // 64 d x 4 quarters
    float p = 0.f;
#pragma unroll 16
    for (int k = q * 64; k < q * 64 + 64; k++) p += ce_w2[d * 256 + k] * gv[k];
    red[tid] = p;
    __syncthreads();
    if (q == 0) g_H2v[d] = red[tid] + red[tid + 1] + red[tid + 2] + red[tid + 3] + ce_b2[d];
}

// ---------------- phase Z: [H1|H2v|H3|H4col] @ W2^T chunks (96 blocks) ----------------
__global__ __launch_bounds__(256) void phaseZ_k(const float* __restrict__ W2)
{
    extern __shared__ float sm[];
    int b = blockIdx.x;
    int c = b / 32, t = b & 31;
    int K0 = c * 128, K1 = (c == 2) ? 385 : (c + 1) * 128;
    auto ld = [&](int i, int k) {
        if (k < 256) {
            int g = i * 256 + k;
            return g_H1s[0][g] + g_H1s[1][g] + g_H1s[2][g] + g_H1s[3][g];
        }
        if (k < 320) return g_H2v[k - 256];
        if (k < 384) return g_H3[i * 64 + (k - 320)];
        return (i < 64) ? g_H4v[i] : 0.f;
    };
    gemm64<false>(sm, ld, W2, 385, K0, K1, (t >> 2) * 64, (t & 3) * 64, g_Zs[c], 256);
}

// ---------------- opln: Z @ op_w^T + op_b, LayerNorm, ELU (128 blocks x 4 rows) ----------------
__global__ __launch_bounds__(256) void opln_k(const float* __restrict__ op_w,
                                              const float* __restrict__ op_b,
                                              const float* __restrict__ ln_g,
                                              const float* __restrict__ ln_b,
                                              float* __restrict__ out)
{
    __shared__ __align__(16) float sA[16][4];
    __shared__ float sB[16][256];
    __shared__ __align__(16) float4 red[256];
    int tid = threadIdx.x;
    int m0 = blockIdx.x * 4;
    float acc[4] = {};
    for (int kc = 0; kc < 256; kc += 16) {
        if (tid < 64) {
            int r = tid >> 4, k = tid & 15;
            int g = (m0 + r) * 256 + kc + k;
            sA[k][r] = g_Zs[0][g] + g_Zs[1][g] + g_Zs[2][g];
        }
#pragma unroll
        for (int s = 0; s < 16; s++) {
            int idx = tid + s * 256;
            int n = idx >> 4, k = idx & 15;
            sB[k][n] = op_w[n * 256 + kc + k];
        }
        __syncthreads();
#pragma unroll
        for (int kk = 0; kk < 16; kk++) {
            float4 a = *(const float4*)&sA[kk][0];
            float bv = sB[kk][tid];
            acc[0] = fmaf(a.x, bv, acc[0]);
            acc[1] = fmaf(a.y, bv, acc[1]);
            acc[2] = fmaf(a.z, bv, acc[2]);
            acc[3] = fmaf(a.w, bv, acc[3]);
        }
        __syncthreads();
    }
    float bias = op_b[tid];
#pragma unroll
    for (int r = 0; r < 4; r++) acc[r] += bias;
    red[tid] = make_float4(acc[0], acc[1], acc[2], acc[3]);
    __syncthreads();
    for (int o = 128; o > 0; o >>= 1) {
        if (tid < o) {
            float4 x = red[tid], y = red[tid + o];
            red[tid] = make_float4(x.x + y.x, x.y + y.y, x.z + y.z, x.w + y.w);
        }
        __syncthreads();
    }
    float4 mu4 = red[0];
    __syncthreads();
    float mu[4] = { mu4.x * (1.f/256.f), mu4.y * (1.f/256.f), mu4.z * (1.f/256.f), mu4.w * (1.f/256.f) };
    float d0 = acc[0] - mu[0], d1 = acc[1] - mu[1], d2 = acc[2] - mu[2], d3 = acc[3] - mu[3];
    red[tid] = make_float4(d0 * d0, d1 * d1, d2 * d2, d3 * d3);
    __syncthreads();
    for (int o = 128; o > 0; o >>= 1) {
        if (tid < o) {
            float4 x = red[tid], y = red[tid + o];
            red[tid] = make_float4(x.x + y.x, x.y + y.y, x.z + y.z, x.w + y.w);
        }
        __syncthreads();
    }
    float4 v4 = red[0];
    float inv[4] = { rsqrtf(v4.x * (1.f/256.f) + 1e-5f), rsqrtf(v4.y * (1.f/256.f) + 1e-5f),
                     rsqrtf(v4.z * (1.f/256.f) + 1e-5f), rsqrtf(v4.w * (1.f/256.f) + 1e-5f) };
    float g = ln_g[tid], bb = ln_b[tid];
    float dd[4] = { d0, d1, d2, d3 };
#pragma unroll
    for (int r = 0; r < 4; r++) {
        float y = dd[r] * inv[r] * g + bb;
        out[(m0 + r) * 256 + tid] = (y > 0.f) ? y : expm1f(y);
    }
}

// ---------------- host side ----------------
extern "C" void kernel_launch(void* const* d_in, const int* in_sizes, int n_in,
                              void* d_out, int out_size)
{
    const float* V       = (const float*)d_in[0];
    const int*   adj     = (const int*)d_in[1];
    const float* prev    = (const float*)d_in[2];
    const float* W1      = (const float*)d_in[3];
    const float* sa0     = (const float*)d_in[4];
    const float* sa1     = (const float*)d_in[5];
    const float* ce_w1   = (const float*)d_in[6];
    const float* ce_b1   = (const float*)d_in[7];
    const float* ce_w2   = (const float*)d_in[8];
    const float* ce_b2   = (const float*)d_in[9];
    const float* ca0     = (const float*)d_in[10];
    const float* ca1     = (const float*)d_in[11];
    const float* te_w1   = (const float*)d_in[12];
    const float* te_b1   = (const float*)d_in[13];
    const float* te_w2   = (const float*)d_in[14];
    const float* te_b2   = (const float*)d_in[15];
    const float* pe_w1   = (const float*)d_in[18];
    const float* pe_b1   = (const float*)d_in[19];
    const float* pe_w2   = (const float*)d_in[20];
    const float* pe_b2   = (const float*)d_in[21];
    const float* W2      = (const float*)d_in[24];
    const float* op_w    = (const float*)d_in[25];
    const float* op_b    = (const float*)d_in[26];
    const float* ln_g    = (const float*)d_in[27];
    const float* ln_b    = (const float*)d_in[28];
    float* out = (float*)d_out;

    const int GSM = 16 * 68 * 2 * 4;   // gemm64 smem

    prep_k   <<<3,   256>>>(adj, ce_w2, ca0, ca1);
    phaseA_k <<<512, 256, GSM>>>(V, prev, W1, ce_w1, te_w1, pe_w1);
    phase2a_k<<<656, 256, GSM>>>(sa0, sa1, ce_b1, te_w2, te_b1, pe_w2, pe_b1);
    phase2b_k<<<515, 256>>>(adj, te_b2, pe_b2);
    phase2c_k<<<640, 256, GSM>>>();
    h2_k     <<<1,   256>>>(ce_w2, ce_b2);
    phaseZ_k <<<96,  256, GSM>>>(W2);
    opln_k   <<<128, 256>>>(op_w, op_b, ln_g, ln_b, out);
}

// round 5
// speedup vs baseline: 1.4618x; 1.0313x over previous
#include <cuda_runtime.h>
#include <math.h>

#define NN 512
#define DF 256
typedef unsigned long long u64;

// ---------------- f32x2 helpers ----------------
__device__ __forceinline__ u64 pk2(float x) {
    u64 r; unsigned xi = __float_as_uint(x);
    asm("mov.b64 %0, {%1, %1};" : "=l"(r) : "r"(xi));
    return r;
}
__device__ __forceinline__ u64 pk2b(float lo, float hi) {
    u64 r; unsigned a = __float_as_uint(lo), b = __float_as_uint(hi);
    asm("mov.b64 %0, {%1, %2};" : "=l"(r) : "r"(a), "r"(b));
    return r;
}
__device__ __forceinline__ float2 unpk(u64 v) {
    unsigned a, b;
    asm("mov.b64 {%0, %1}, %2;" : "=r"(a), "=r"(b) : "l"(v));
    return make_float2(__uint_as_float(a), __uint_as_float(b));
}
__device__ __forceinline__ u64 ffma2(u64 a, u64 b, u64 c) {
    u64 r;
    asm("fma.rn.f32x2 %0, %1, %2, %3;" : "=l"(r) : "l"(a), "l"(b), "l"(c));
    return r;
}
__device__ __forceinline__ u64 fadd2(u64 a, u64 b) {
    u64 r;
    asm("add.rn.f32x2 %0, %1, %2;" : "=l"(r) : "l"(a), "l"(b));
    return r;
}
#define ABS2 0x7fffffff7fffffffULL

// ---------------- scratch ----------------
__device__ float g_Wh1s[2][NN*DF];
__device__ float g_Ars[2][NN*DF];
__device__ float g_Brs[2][NN*DF];
__device__ float g_hidTs[4][NN*DF];
__device__ float g_hidPs[6][NN*DF];
__device__ float g_tfs[2][NN*64];
__device__ float g_cfs[2][NN*64];
__device__ float g_H1s[4][NN*DF];
__device__ float g_Zs[3][NN*DF];
__device__ float g_Wh1F[NN*DF];
__device__ float g_ArF[NN*DF];
__device__ float g_BrF[NN*DF];
__device__ float g_e0[NN], g_e1[NN];
__device__ float g_P[NN*NN];
__device__ float g_u[DF];
__device__ float g_red[256];
__device__ float g_MS[2];
__device__ float g_s2[NN*NN];
__device__ float g_part[512*DF];
__device__ float g_H2v[64];
__device__ float g_H3[NN*64];
__device__ int   g_i0[NN], g_i1[NN];
__device__ float g_H4v[64];

// ---------------- 64x64 GEMM tile (f32x2), K range [K0,K1) ----------------
template <bool BNN, class AL>
__device__ __forceinline__ void gemm64f2(
    float* sm, AL aload, const float* __restrict__ B, int ldb,
    int K0, int K1, int m0, int n0, float* __restrict__ C, int ldc)
{
    float (*sA)[68] = (float(*)[68])sm;
    float (*sB)[68] = (float(*)[68])(sm + 16*68);
    int tid = threadIdx.x, tx = tid & 15, ty = tid >> 4;
    u64 acc[4][2] = {};
    for (int kc = K0; kc < K1; kc += 16) {
#pragma unroll
        for (int s = 0; s < 4; s++) {
            int idx = tid + s * 256;
            int r = idx >> 4, k = idx & 15;
            int gk = kc + k;
            sA[k][r] = (gk < K1) ? aload(m0 + r, gk) : 0.f;
            if (BNN) {
                int kb = idx >> 6, nb = idx & 63;
                int gkb = kc + kb;
                sB[kb][nb] = (gkb < K1) ? B[gkb * ldb + n0 + nb] : 0.f;
            } else {
                sB[k][r] = (gk < K1) ? B[(n0 + r) * ldb + gk] : 0.f;
            }
        }
        __syncthreads();
#pragma unroll
        for (int kk = 0; kk < 16; kk++) {
            float4 av = *(const float4*)&sA[kk][ty << 2];
            ulonglong2 bv = *(const ulonglong2*)&sB[kk][tx << 2];
            u64 a0 = pk2(av.x), a1 = pk2(av.y), a2 = pk2(av.z), a3 = pk2(av.w);
            acc[0][0] = ffma2(a0, bv.x, acc[0][0]); acc[0][1] = ffma2(a0, bv.y, acc[0][1]);
            acc[1][0] = ffma2(a1, bv.x, acc[1][0]); acc[1][1] = ffma2(a1, bv.y, acc[1][1]);
            acc[2][0] = ffma2(a2, bv.x, acc[2][0]); acc[2][1] = ffma2(a2, bv.y, acc[2][1]);
            acc[3][0] = ffma2(a3, bv.x, acc[3][0]); acc[3][1] = ffma2(a3, bv.y, acc[3][1]);
        }
        __syncthreads();
    }
#pragma unroll
    for (int i = 0; i < 4; i++)
#pragma unroll
        for (int p = 0; p < 2; p++) {
            float2 v = unpk(acc[i][p]);
            int gm = m0 + ty * 4 + i, gn = n0 + tx * 4 + 2 * p;
            C[gm * ldc + gn] = v.x;
            C[gm * ldc + gn + 1] = v.y;
        }
}

// ---------------- prep: neighbor indices (ballot) + u ----------------
__global__ __launch_bounds__(256) void prep_k(const int* __restrict__ adj,
                                              const float* __restrict__ ce_w2,
                                              const float* __restrict__ ca0,
                                              const float* __restrict__ ca1)
{
    int b = blockIdx.x, tid = threadIdx.x;
    if (b < 64) {
        int w = tid >> 5, lane = tid & 31;
        int row = b * 8 + w;
        int a = -1, c = -1;
        for (int l = 0; l < 16; l++) {
            int v = adj[row * NN + l * 32 + lane];
            unsigned mask = __ballot_sync(0xffffffffu, v == 1);
            if (mask) {
                if (a < 0) {
                    a = l * 32 + __ffs(mask) - 1;
                    unsigned m2 = mask & (mask - 1);
                    if (m2) c = l * 32 + __ffs(m2) - 1;
                } else {
                    c = l * 32 + __ffs(mask) - 1;
                }
                if (c >= 0) break;
            }
        }
        if (lane == 0) { g_i0[row] = (a < 0) ? NN : a; g_i1[row] = (c < 0) ? NN : c; }
    } else {
        __shared__ float sc[64];
        if (tid < 64) sc[tid] = ca0[tid] + ca1[tid];
        __syncthreads();
        float acc = 0.f;
#pragma unroll 8
        for (int d = 0; d < 64; d++) acc += ce_w2[d * 256 + tid] * sc[d];
        g_u[tid] = acc;
    }
}

// ---------------- phase A: first-layer GEMMs (512 blocks) ----------------
__global__ __launch_bounds__(256) void phaseA_k(
    const float* __restrict__ V, const float* __restrict__ prev,
    const float* __restrict__ W1,
    const float* __restrict__ ce_w1,
    const float* __restrict__ te_w1,
    const float* __restrict__ pe_w1)
{
    extern __shared__ float sm[];
    int b = blockIdx.x;
    auto ldV = [&](int i, int k) { return V[i * 256 + k]; };
    if (b < 64) {
        int c = b >> 5, t = b & 31;
        gemm64f2<false>(sm, ldV, W1, 256, c * 128, c * 128 + 128,
                        (t >> 2) * 64, (t & 3) * 64, g_Wh1s[c], 256);
    } else if (b < 128) {
        b -= 64; int c = b >> 5, t = b & 31;
        gemm64f2<false>(sm, ldV, ce_w1, 512, c * 128, c * 128 + 128,
                        (t >> 2) * 64, (t & 3) * 64, g_Ars[c], 256);
    } else if (b < 192) {
        b -= 128; int c = b >> 5, t = b & 31;
        gemm64f2<false>(sm, ldV, ce_w1 + 256, 512, c * 128, c * 128 + 128,
                        (t >> 2) * 64, (t & 3) * 64, g_Brs[c], 256);
    } else if (b < 320) {
        b -= 192; int c = b >> 5, t = b & 31;
        auto ld2 = [&](int i, int k) { return (k < 256) ? V[i * 256 + k] : prev[i * 256 + k - 256]; };
        gemm64f2<false>(sm, ld2, te_w1, 512, c * 128, c * 128 + 128,
                        (t >> 2) * 64, (t & 3) * 64, g_hidTs[c], 256);
    } else {
        b -= 320; int c = b >> 5, t = b & 31;
        auto ld3 = [&](int i, int k) {
            if (k < 256) return V[i * 256 + k];
            int i1 = g_i1[i];
            if (i1 >= NN) return 0.f;
            if (k < 512) return V[min(g_i0[i], NN - 1) * 256 + (k - 256)];
            return V[min(i1, NN - 1) * 256 + (k - 512)];
        };
        gemm64f2<false>(sm, ld3, pe_w1, 768, c * 128, c * 128 + 128,
                        (t >> 2) * 64, (t & 3) * 64, g_hidPs[c], 256);
    }
}

// ---------------- phase 2a: pair_score(abs-trick) + e01 + tf + cf + finish (272 blocks) ----------------
__global__ __launch_bounds__(256) void phase2a_k(
    const float* __restrict__ sa0, const float* __restrict__ sa1,
    const float* __restrict__ ce_b1,
    const float* __restrict__ te_w2, const float* __restrict__ te_b1,
    const float* __restrict__ pe_w2, const float* __restrict__ pe_b1)
{
    extern __shared__ float sm[];
    int b = blockIdx.x, tid = threadIdx.x;
    if (b < 128) {
        // pair_score: 64 i x 32 j tile, K=256.
        // s2[i,j] = cA[i] + cB[j] + sum_k 0.5*u_k*|Ar[i,k]+Br[j,k]|
        __shared__ __align__(16) float sA[16][68];
        __shared__ __align__(16) u64  sB2[16][16];
        __shared__ u64  su2[16];
        __shared__ float cAs[64], cBs[32];
        __shared__ float rm[256], rs[256];
        int tx = tid & 15, ty = tid >> 4;
        int ib = (b >> 4) * 64, jb = (b & 15) * 32;
        int w = tid >> 5, lane = tid & 31;

        // cA: warps 0..7, 8 i-rows each; cB: warps 0..3, 8 j-rows each
        {
#pragma unroll
            for (int r = 0; r < 8; r++) {
                int i = ib + w * 8 + r;
                float s = 0.f;
#pragma unroll
                for (int t = 0; t < 8; t++) {
                    int k = lane + t * 32;
                    float a = g_Ars[0][i * 256 + k] + g_Ars[1][i * 256 + k] + ce_b1[k];
                    s += a * (0.5f * g_u[k]);
                }
#pragma unroll
                for (int o = 16; o > 0; o >>= 1) s += __shfl_down_sync(0xffffffffu, s, o);
                if (lane == 0) cAs[w * 8 + r] = s;
            }
            if (w < 4) {
#pragma unroll
                for (int r = 0; r < 8; r++) {
                    int j = jb + w * 8 + r;
                    float s = 0.f;
#pragma unroll
                    for (int t = 0; t < 8; t++) {
                        int k = lane + t * 32;
                        float bb = g_Brs[0][j * 256 + k] + g_Brs[1][j * 256 + k];
                        s += bb * (0.5f * g_u[k]);
                    }
#pragma unroll
                    for (int o = 16; o > 0; o >>= 1) s += __shfl_down_sync(0xffffffffu, s, o);
                    if (lane == 0) cBs[w * 8 + r] = s;
                }
            }
        }
        __syncthreads();

        u64 acc[4] = {};
        for (int kc = 0; kc < 256; kc += 16) {
#pragma unroll
            for (int s = 0; s < 4; s++) {
                int idx = tid + s * 256;
                int r = idx >> 4, k = idx & 15;
                int gi = (ib + r) * 256 + kc + k;
                sA[k][r] = g_Ars[0][gi] + g_Ars[1][gi] + ce_b1[kc + k];
            }
            {   // sB2[k][jp] = (Br[jb+2jp][kc+k], Br[jb+2jp+1][kc+k])
                int k = tid & 15, jp = tid >> 4;
                int r0 = (jb + 2 * jp) * 256 + kc + k;
                int r1 = r0 + 256;
                float b0 = g_Brs[0][r0] + g_Brs[1][r0];
                float b1 = g_Brs[0][r1] + g_Brs[1][r1];
                sB2[k][jp] = pk2b(b0, b1);
            }
            if (tid < 16) su2[tid] = pk2(0.5f * g_u[kc + tid]);
            __syncthreads();
#pragma unroll
            for (int kk = 0; kk < 16; kk++) {
                float4 av = *(const float4*)&sA[kk][ty << 2];
                u64 b2 = sB2[kk][tx];
                u64 uu = su2[kk];
                u64 t0 = fadd2(pk2(av.x), b2) & ABS2;
                u64 t1 = fadd2(pk2(av.y), b2) & ABS2;
                u64 t2 = fadd2(pk2(av.z), b2) & ABS2;
                u64 t3 = fadd2(pk2(av.w), b2) & ABS2;
                acc[0] = ffma2(t0, uu, acc[0]);
                acc[1] = ffma2(t1, uu, acc[1]);
                acc[2] = ffma2(t2, uu, acc[2]);
                acc[3] = ffma2(t3, uu, acc[3]);
            }
            __syncthreads();
        }
        int j0 = jb + 2 * tx, j1 = j0 + 1;
        float cb0 = cBs[2 * tx], cb1 = cBs[2 * tx + 1];
        float m = -3.402823466e38f, sum = 0.f;
#pragma unroll
        for (int i = 0; i < 4; i++) {
            int gi = ib + ty * 4 + i;
            float ca = cAs[ty * 4 + i];
            float2 p = unpk(acc[i]);
            float v0 = (gi == j0) ? -INFINITY : (p.x + ca + cb0);
            float v1 = (gi == j1) ? -INFINITY : (p.y + ca + cb1);
            g_s2[gi * NN + j0] = v0;
            g_s2[gi * NN + j1] = v1;
            float nm = fmaxf(m, fmaxf(v0, v1));
            sum = sum * __expf(m - nm) + __expf(v0 - nm) + __expf(v1 - nm);
            m = nm;
        }
        rm[tid] = m; rs[tid] = sum; __syncthreads();
        for (int o = 128; o > 0; o >>= 1) {
            if (tid < o) {
                float m2 = rm[tid + o], s2v = rs[tid + o];
                float M = fmaxf(rm[tid], m2);
                rs[tid] = rs[tid] * __expf(rm[tid] - M) + s2v * __expf(m2 - M);
                rm[tid] = M;
            }
            __syncthreads();
        }
        if (tid == 0) { g_red[2 * b] = rm[0]; g_red[2 * b + 1] = rs[0]; }
    } else if (b < 192) {
        int eb = b - 128;
        int w = tid >> 5, lane = tid & 31;
        int row = eb * 8 + w;
        float a0 = 0.f, a1 = 0.f;
#pragma unroll
        for (int l = 0; l < 8; l++) {
            int k = lane + l * 32;
            float a = g_Wh1s[0][row * 256 + k] + g_Wh1s[1][row * 256 + k];
            a0 += a * sa0[k];
            a1 += a * sa1[k];
        }
#pragma unroll
        for (int o = 16; o > 0; o >>= 1) {
            a0 += __shfl_down_sync(0xffffffffu, a0, o);
            a1 += __shfl_down_sync(0xffffffffu, a1, o);
        }
        if (lane == 0) { g_e0[row] = a0; g_e1[row] = a1; }
    } else if (b < 208) {
        int t = b - 192; int c = t >> 3, mt = t & 7;
        auto ld = [&](int i, int k) {
            int g = i * 256 + k;
            return fmaxf(g_hidTs[0][g] + g_hidTs[1][g] + g_hidTs[2][g] + g_hidTs[3][g] + te_b1[k], 0.f);
        };
        gemm64f2<false>(sm, ld, te_w2, 256, c * 128, c * 128 + 128, mt * 64, 0, g_tfs[c], 64);
    } else if (b < 224) {
        int t = b - 208; int c = t >> 3, mt = t & 7;
        auto ld = [&](int i, int k) {
            int g = i * 256 + k;
            return fmaxf(g_hidPs[0][g] + g_hidPs[1][g] + g_hidPs[2][g] + g_hidPs[3][g]
                         + g_hidPs[4][g] + g_hidPs[5][g] + pe_b1[k], 0.f);
        };
        gemm64f2<false>(sm, ld, pe_w2, 256, c * 128, c * 128 + 128, mt * 64, 0, g_cfs[c], 64);
    } else {
        int fb = b - 224;
        int tens = fb >> 4, sub = fb & 15;
        int base = sub * 8192;
#pragma unroll 4
        for (int j = 0; j < 32; j++) {
            int idx = base + j * 256 + tid;
            if (tens == 0) g_Wh1F[idx] = g_Wh1s[0][idx] + g_Wh1s[1][idx];
            else if (tens == 1) g_ArF[idx] = g_Ars[0][idx] + g_Ars[1][idx] + ce_b1[tid];
            else g_BrF[idx] = g_Brs[0][idx] + g_Brs[1][idx];
        }
    }
}

// ---------------- phase 2b: smax_final + H3 + H4 + gatP (515 blocks) ----------------
__global__ __launch_bounds__(256) void phase2b_k(const int* __restrict__ adj,
                                                 const float* __restrict__ te_b2,
                                                 const float* __restrict__ pe_b2)
{
    __shared__ float r1[256], r2[256];
    int b = blockIdx.x, tid = threadIdx.x;
    if (b == 0) {
        float m = (tid < 128) ? g_red[2 * tid] : -INFINITY;
        float s = (tid < 128) ? g_red[2 * tid + 1] : 0.f;
        r1[tid] = m; r2[tid] = s; __syncthreads();
        for (int o = 128; o > 0; o >>= 1) {
            if (tid < o) {
                float m2 = r1[tid + o], s2v = r2[tid + o];
                float MM = fmaxf(r1[tid], m2);
                r2[tid] = r2[tid] * __expf(r1[tid] - MM) + s2v * __expf(m2 - MM);
                r1[tid] = MM;
            }
            __syncthreads();
        }
        if (tid == 0) { g_MS[0] = r1[0]; g_MS[1] = r2[0]; }
    } else if (b == 1) {
        int t = tid & 63, s = tid >> 6;
        float bias = te_b2[t];
        int i0 = s * 128;
        float p0 = 0.f, p1 = 0.f, p2 = 0.f, p3 = 0.f;
#pragma unroll 8
        for (int i = i0; i < i0 + 128; i += 4) {
            p0 += g_tfs[0][i * 64 + t] + g_tfs[1][i * 64 + t];
            p1 += g_tfs[0][(i+1) * 64 + t] + g_tfs[1][(i+1) * 64 + t];
            p2 += g_tfs[0][(i+2) * 64 + t] + g_tfs[1][(i+2) * 64 + t];
            p3 += g_tfs[0][(i+3) * 64 + t] + g_tfs[1][(i+3) * 64 + t];
        }
        r1[s * 64 + t] = p0 + p1 + p2 + p3 + 128.f * bias;
        __syncthreads();
        float acc = 0.f;
        for (int q = 0; q < s; q++) acc += r1[q * 64 + t];
#pragma unroll 16
        for (int i = i0; i < i0 + 128; i++) {
            acc += g_tfs[0][i * 64 + t] + g_tfs[1][i * 64 + t] + bias;
            g_H3[i * 64 + t] = acc / (float)(i + 1);
        }
    } else if (b == 2) {
        int t = tid & 63, s = tid >> 6;
        float bias = pe_b2[t];
        int i0 = s * 128;
        float p0 = 0.f, p1 = 0.f;
#pragma unroll 8
        for (int i = i0; i < i0 + 128; i += 2) {
            p0 += g_cfs[0][i * 64 + t] + g_cfs[1][i * 64 + t];
            p1 += g_cfs[0][(i+1) * 64 + t] + g_cfs[1][(i+1) * 64 + t];
        }
        r1[s * 64 + t] = p0 + p1 + 128.f * bias;
        __syncthreads();
        if (s == 0) g_H4v[t] = r1[t] + r1[64 + t] + r1[128 + t] + r1[192 + t];
    } else {
        int i = b - 3;
        float e0i = g_e0[i];
        float sl[2];
        float m = -3.402823466e38f;
#pragma unroll
        for (int s = 0; s < 2; s++) {
            int j = tid + s * 256;
            float v = (adj[i * NN + j] != 0) ? (e0i + g_e1[j]) : -INFINITY;
            sl[s] = v;
            m = fmaxf(m, v);
        }
        // warp reduce then cross-warp
        int lane = tid & 31, w = tid >> 5;
#pragma unroll
        for (int o = 16; o > 0; o >>= 1) m = fmaxf(m, __shfl_xor_sync(0xffffffffu, m, o));
        if (lane == 0) r1[w] = m;
        __syncthreads();
        m = fmaxf(fmaxf(fmaxf(r1[0], r1[1]), fmaxf(r1[2], r1[3])),
                  fmaxf(fmaxf(r1[4], r1[5]), fmaxf(r1[6], r1[7])));
        float e[2];
        float sum = 0.f;
#pragma unroll
        for (int s = 0; s < 2; s++) { e[s] = __expf(sl[s] - m); sum += e[s]; }
#pragma unroll
        for (int o = 16; o > 0; o >>= 1) sum += __shfl_xor_sync(0xffffffffu, sum, o);
        if (lane == 0) r2[w] = sum;
        __syncthreads();
        sum = r2[0] + r2[1] + r2[2] + r2[3] + r2[4] + r2[5] + r2[6] + r2[7];
        float inv = 1.f / sum;
#pragma unroll
        for (int s = 0; s < 2; s++) g_P[i * NN + tid + s * 256] = e[s] * inv;
    }
}

// ---------------- phase 2c: H1 chunks + pair_acc (640 blocks) ----------------
__global__ __launch_bounds__(256) void phase2c_k()
{
    extern __shared__ float sm[];
    int b = blockIdx.x, tid = threadIdx.x;
    if (b < 128) {
        int c = b >> 5, t = b & 31;
        auto ld = [&](int i, int k) { return g_P[i * 512 + k]; };
        gemm64f2<true>(sm, ld, g_Wh1F, 256, c * 128, c * 128 + 128,
                       (t >> 2) * 64, (t & 3) * 64, g_H1s[c], 256);
    } else {
        int pb = b - 128;
        int i0 = (pb & 63) * 8;
        int jb = (pb >> 6) * 64;
        float M = g_MS[0], invS = 1.f / g_MS[1];
        float a[8];
#pragma unroll
        for (int ii = 0; ii < 8; ii++) a[ii] = g_ArF[(i0 + ii) * 256 + tid];
        float acc = 0.f;
        float* sw = sm;
        int li = tid >> 5, lj = tid & 31;
        for (int jc = jb; jc < jb + 64; jc += 32) {
            sw[li * 32 + lj] = __expf(g_s2[(i0 + li) * NN + jc + lj] - M) * invS;
            __syncthreads();
#pragma unroll 4
            for (int jj = 0; jj < 32; jj++) {
                float bb = g_BrF[(jc + jj) * 256 + tid];
#pragma unroll
                for (int ii = 0; ii < 8; ii++)
                    acc += sw[ii * 32 + jj] * fmaxf(a[ii] + bb, 0.f);
            }
            __syncthreads();
        }
        g_part[pb * 256 + tid] = acc;
    }
}

// ---------------- h2 ----------------
__global__ __launch_bounds__(256) void h2_k(const float* __restrict__ ce_w2,
                                            const float* __restrict__ ce_b2)
{
    __shared__ float gv[256];
    __shared__ float red[256];
    int tid = threadIdx.x;
    float acc = 0.f;
#pragma unroll 8
    for (int r = 0; r < 512; r++) acc += g_part[r * 256 + tid];
    gv[tid] = acc;
    __syncthreads();
    int d = tid >> 2, q = tid & 3;
    float p = 0.f;
#pragma unroll 16
    for (int k = q * 64; k < q * 64 + 64; k++) p += ce_w2[d * 256 + k] * gv[k];
    red[tid] = p;
    __syncthreads();
    if (q == 0) g_H2v[d] = red[tid] + red[tid + 1] + red[tid + 2] + red[tid + 3] + ce_b2[d];
}

// ---------------- phase Z ----------------
__global__ __launch_bounds__(256) void phaseZ_k(const float* __restrict__ W2)
{
    extern __shared__ float sm[];
    int b = blockIdx.x;
    int c = b / 32, t = b & 31;
    int K0 = c * 128, K1 = (c == 2) ? 385 : (c + 1) * 128;
    auto ld = [&](int i, int k) {
        if (k < 256) {
            int g = i * 256 + k;
            return g_H1s[0][g] + g_H1s[1][g] + g_H1s[2][g] + g_H1s[3][g];
        }
        if (k < 320) return g_H2v[k - 256];
        if (k < 384) return g_H3[i * 64 + (k - 320)];
        return (i < 64) ? g_H4v[i] : 0.f;
    };
    gemm64f2<false>(sm, ld, W2, 385, K0, K1, (t >> 2) * 64, (t & 3) * 64, g_Zs[c], 256);
}

// ---------------- opln ----------------
__global__ __launch_bounds__(256) void opln_k(const float* __restrict__ op_w,
                                              const float* __restrict__ op_b,
                                              const float* __restrict__ ln_g,
                                              const float* __restrict__ ln_b,
                                              float* __restrict__ out)
{
    __shared__ __align__(16) float sA[16][4];
    __shared__ float sB[16][256];
    __shared__ __align__(16) float4 red[256];
    int tid = threadIdx.x;
    int m0 = blockIdx.x * 4;
    float acc[4] = {};
    for (int kc = 0; kc < 256; kc += 16) {
        if (tid < 64) {
            int r = tid >> 4, k = tid & 15;
            int g = (m0 + r) * 256 + kc + k;
            sA[k][r] = g_Zs[0][g] + g_Zs[1][g] + g_Zs[2][g];
        }
#pragma unroll
        for (int s = 0; s < 16; s++) {
            int idx = tid + s * 256;
            int n = idx >> 4, k = idx & 15;
            sB[k][n] = op_w[n * 256 + kc + k];
        }
        __syncthreads();
#pragma unroll
        for (int kk = 0; kk < 16; kk++) {
            float4 a = *(const float4*)&sA[kk][0];
            float bv = sB[kk][tid];
            acc[0] = fmaf(a.x, bv, acc[0]);
            acc[1] = fmaf(a.y, bv, acc[1]);
            acc[2] = fmaf(a.z, bv, acc[2]);
            acc[3] = fmaf(a.w, bv, acc[3]);
        }
        __syncthreads();
    }
    float bias = op_b[tid];
#pragma unroll
    for (int r = 0; r < 4; r++) acc[r] += bias;
    red[tid] = make_float4(acc[0], acc[1], acc[2], acc[3]);
    __syncthreads();
    for (int o = 128; o > 0; o >>= 1) {
        if (tid < o) {
            float4 x = red[tid], y = red[tid + o];
            red[tid] = make_float4(x.x + y.x, x.y + y.y, x.z + y.z, x.w + y.w);
        }
        __syncthreads();
    }
    float4 mu4 = red[0];
    __syncthreads();
    float mu[4] = { mu4.x * (1.f/256.f), mu4.y * (1.f/256.f), mu4.z * (1.f/256.f), mu4.w * (1.f/256.f) };
    float d0 = acc[0] - mu[0], d1 = acc[1] - mu[1], d2 = acc[2] - mu[2], d3 = acc[3] - mu[3];
    red[tid] = make_float4(d0 * d0, d1 * d1, d2 * d2, d3 * d3);
    __syncthreads();
    for (int o = 128; o > 0; o >>= 1) {
        if (tid < o) {
            float4 x = red[tid], y = red[tid + o];
            red[tid] = make_float4(x.x + y.x, x.y + y.y, x.z + y.z, x.w + y.w);
        }
        __syncthreads();
    }
    float4 v4 = red[0];
    float inv[4] = { rsqrtf(v4.x * (1.f/256.f) + 1e-5f), rsqrtf(v4.y * (1.f/256.f) + 1e-5f),
                     rsqrtf(v4.z * (1.f/256.f) + 1e-5f), rsqrtf(v4.w * (1.f/256.f) + 1e-5f) };
    float g = ln_g[tid], bb = ln_b[tid];
    float dd[4] = { d0, d1, d2, d3 };
#pragma unroll
    for (int r = 0; r < 4; r++) {
        float y = dd[r] * inv[r] * g + bb;
        out[(m0 + r) * 256 + tid] = (y > 0.f) ? y : expm1f(y);
    }
}

// ---------------- host ----------------
extern "C" void kernel_launch(void* const* d_in, const int* in_sizes, int n_in,
                              void* d_out, int out_size)
{
    const float* V       = (const float*)d_in[0];
    const int*   adj     = (const int*)d_in[1];
    const float* prev    = (const float*)d_in[2];
    const float* W1      = (const float*)d_in[3];
    const float* sa0     = (const float*)d_in[4];
    const float* sa1     = (const float*)d_in[5];
    const float* ce_w1   = (const float*)d_in[6];
    const float* ce_b1   = (const float*)d_in[7];
    const float* ce_w2   = (const float*)d_in[8];
    const float* ce_b2   = (const float*)d_in[9];
    const float* ca0     = (const float*)d_in[10];
    const float* ca1     = (const float*)d_in[11];
    const float* te_w1   = (const float*)d_in[12];
    const float* te_b1   = (const float*)d_in[13];
    const float* te_w2   = (const float*)d_in[14];
    const float* te_b2   = (const float*)d_in[15];
    const float* pe_w1   = (const float*)d_in[18];
    const float* pe_b1   = (const float*)d_in[19];
    const float* pe_w2   = (const float*)d_in[20];
    const float* pe_b2   = (const float*)d_in[21];
    const float* W2      = (const float*)d_in[24];
    const float* op_w    = (const float*)d_in[25];
    const float* op_b    = (const float*)d_in[26];
    const float* ln_g    = (const float*)d_in[27];
    const float* ln_b    = (const float*)d_in[28];
    float* out = (float*)d_out;

    const int GSM = 16 * 68 * 2 * 4;

    prep_k   <<<65,  256>>>(adj, ce_w2, ca0, ca1);
    phaseA_k <<<512, 256, GSM>>>(V, prev, W1, ce_w1, te_w1, pe_w1);
    phase2a_k<<<272, 256, GSM>>>(sa0, sa1, ce_b1, te_w2, te_b1, pe_w2, pe_b1);
    phase2b_k<<<515, 256>>>(adj, te_b2, pe_b2);
    phase2c_k<<<640, 256, GSM>>>();
    h2_k     <<<1,   256>>>(ce_w2, ce_b2);
    phaseZ_k <<<96,  256, GSM>>>(W2);
    opln_k   <<<128, 256>>>(op_w, op_b, ln_g, ln_b, out);
}